// round 2
// baseline (speedup 1.0000x reference)
#include <cuda_runtime.h>
#include <cstdint>

#define B_ 128
#define T_ 256
#define F_ 128
#define NCAT_ 32
#define CARD_ 16
#define E_ 8
#define H_ 512
#define INPUT_LEN_ 352
#define NCONT_ 96
#define BT_ (B_*T_)
#define G4H_ 2048
#define NBLK_ 128   // persistent grid size

typedef unsigned long long ull;

// ---------------- scratch (device globals: allocation-free rule) ----------------
__device__ float g_xin[(size_t)BT_*INPUT_LEN_];   // 46 MB
__device__ float g_x  [(size_t)BT_*H_];           // 67 MB
__device__ float g_X0 [(size_t)BT_*G4H_];         // 268 MB: x@Wih0^T + bih0 + bhh0
__device__ float g_WT_ih0[H_*G4H_];               // [k][n] transposes
__device__ float g_WT_hh0[H_*G4H_];
__device__ float g_WT_1 [H_*G4H_];                // (Wih1+Whh1)^T
__device__ float g_b0[G4H_];                      // bih0+bhh0 (folded into X0)
__device__ float g_b1[G4H_];                      // bih1+bhh1
__device__ float g_h [B_*H_];
__device__ float g_h0[B_*H_];
__device__ float g_c [B_*H_];
__device__ unsigned g_bar_count = 0;
__device__ unsigned g_bar_gen   = 0;

// ---------------- helpers ----------------
__device__ __forceinline__ ull pack2(float x, float y) {
    ull r; asm("mov.b64 %0, {%1, %2};" : "=l"(r) : "f"(x), "f"(y)); return r;
}
__device__ __forceinline__ float2 unpack2(ull v) {
    float2 r; asm("mov.b64 {%0, %1}, %2;" : "=f"(r.x), "=f"(r.y) : "l"(v)); return r;
}
// packed dual-FMA: d = a*b + d  (two f32 lanes per instruction)
__device__ __forceinline__ void fma2(ull& d, ull a, ull b) {
    asm("fma.rn.f32x2 %0, %1, %2, %0;" : "+l"(d) : "l"(a), "l"(b));
}
__device__ __forceinline__ float sigf(float x) { return 1.0f / (1.0f + __expf(-x)); }

// grid-wide barrier (all NBLK_ CTAs co-resident: grid <= SM count, 1 small CTA/SM)
__device__ __forceinline__ void gsync() {
    __syncthreads();
    if (threadIdx.x == 0) {
        volatile unsigned* genp = &g_bar_gen;
        unsigned gen = *genp;
        __threadfence();
        unsigned t = atomicAdd(&g_bar_count, 1u);
        if (t == (unsigned)NBLK_ - 1u) {
            atomicExch(&g_bar_count, 0u);
            __threadfence();
            atomicAdd(&g_bar_gen, 1u);
        } else {
            while (*genp == gen) { __nanosleep(32); }
        }
        __threadfence();
    }
    __syncthreads();
}

// ---------------- prep: weight transposes + bias sums ----------------
__global__ void prep_kernel(const float* __restrict__ Wih0, const float* __restrict__ Whh0,
                            const float* __restrict__ Wih1, const float* __restrict__ Whh1,
                            const float* __restrict__ bih0, const float* __restrict__ bhh0,
                            const float* __restrict__ bih1, const float* __restrict__ bhh1) {
    int n = blockIdx.x;      // 0..2047 (gate-row)
    int k = threadIdx.x;     // 0..511
    g_WT_ih0[k*G4H_ + n] = Wih0[n*H_ + k];
    g_WT_hh0[k*G4H_ + n] = Whh0[n*H_ + k];
    g_WT_1 [k*G4H_ + n]  = Wih1[n*H_ + k] + Whh1[n*H_ + k];
    if (k == 0) {
        g_b0[n] = bih0[n] + bhh0[n];
        g_b1[n] = bih1[n] + bhh1[n];
    }
}

// ---------------- build xin: embedding gather + cont interleave ----------------
__global__ void build_xin_kernel(const int* __restrict__ unscaled,
                                 const float* __restrict__ scaled,
                                 const float* __restrict__ emb) {
    int bt = blockIdx.x;
    int i  = threadIdx.x;             // 0..351
    int k  = i / 11;                  // categorical group
    int j  = i - k*11;                // 0..7 emb, 8..10 cont
    float v;
    if (j < 8) {
        int cid = unscaled[(size_t)bt*F_ + 4*k];
        v = emb[(k*CARD_ + cid)*E_ + j];
    } else {
        v = scaled[(size_t)bt*F_ + 4*k + (j - 8) + 1];
    }
    g_xin[(size_t)bt*INPUT_LEN_ + i] = v;
}

// ---------------- generic fp32x2 tiled GEMM: C = act(A[M,K] @ W[K,N] + bias) ----------------
// tile: 128m x 64n x 32k, 256 threads, 4m x 8n per thread
template<bool RELU>
__device__ __forceinline__ void gemm_core(const float* __restrict__ A,
                                          const float* __restrict__ Wg,
                                          const float* __restrict__ bias,
                                          float* __restrict__ C, int K, int N) {
    __shared__ float AsT[32*132];   // [k][m], stride 132 keeps float4 alignment
    __shared__ float Ws [32*64];    // [k][n]
    const int m0 = blockIdx.x * 128;
    const int n0 = blockIdx.y * 64;
    const int tid = threadIdx.x, lane = tid & 31, wid = tid >> 5;
    ull acc[4][4];
    #pragma unroll
    for (int a = 0; a < 4; a++)
        #pragma unroll
        for (int b = 0; b < 4; b++) acc[a][b] = 0ull;

    for (int kb = 0; kb < K; kb += 32) {
        {
            int k = tid & 31, mq = tid >> 5;
            #pragma unroll
            for (int i = 0; i < 16; i++)
                AsT[k*132 + mq + i*8] = A[(size_t)(m0 + mq + i*8)*K + kb + k];
            int n = tid & 63, kq = tid >> 6;
            #pragma unroll
            for (int i = 0; i < 8; i++)
                Ws[(kq*8 + i)*64 + n] = Wg[(size_t)(kb + kq*8 + i)*N + n0 + n];
        }
        __syncthreads();
        #pragma unroll
        for (int kk = 0; kk < 32; kk++) {
            float4 a4 = *(const float4*)(AsT + kk*132 + lane*4);
            const ulonglong2* wp = (const ulonglong2*)(Ws + kk*64 + wid*8);
            ulonglong2 wA = wp[0], wB = wp[1];
            float am[4] = {a4.x, a4.y, a4.z, a4.w};
            #pragma unroll
            for (int mi = 0; mi < 4; mi++) {
                ull ap = pack2(am[mi], am[mi]);
                fma2(acc[mi][0], ap, wA.x);
                fma2(acc[mi][1], ap, wA.y);
                fma2(acc[mi][2], ap, wB.x);
                fma2(acc[mi][3], ap, wB.y);
            }
        }
        __syncthreads();
    }
    const int nb = n0 + wid*8;
    float bv[8];
    #pragma unroll
    for (int j = 0; j < 8; j++) bv[j] = bias[nb + j];
    #pragma unroll
    for (int mi = 0; mi < 4; mi++) {
        int row = m0 + lane*4 + mi;
        float* crow = C + (size_t)row*N + nb;
        #pragma unroll
        for (int p = 0; p < 4; p++) {
            float2 v = unpack2(acc[mi][p]);
            v.x += bv[2*p]; v.y += bv[2*p + 1];
            if (RELU) { v.x = fmaxf(v.x, 0.0f); v.y = fmaxf(v.y, 0.0f); }
            *(float2*)(crow + 2*p) = v;
        }
    }
}

__global__ void __launch_bounds__(256) gemm1_kernel(const float* __restrict__ W_in,
                                                    const float* __restrict__ b_in) {
    gemm_core<true>(g_xin, W_in, b_in, g_x, INPUT_LEN_, H_);     // x = relu(xin@W_in+b)
}
__global__ void __launch_bounds__(256) gemm2_kernel() {
    gemm_core<false>(g_x, g_WT_ih0, g_b0, g_X0, H_, G4H_);       // X0 = x@Wih0^T + b0
}

// ---------------- persistent LSTM ----------------
// CTA (mtile, ntile): batches mtile*32..+31, hidden units ntile*16..+15, all 4 gates.
// Ws smem layout reordered so thread wid owns cols [wid*8 .. wid*8+7] = {g0u0,g0u1,g1u0,...}
template<bool USE_X0>
__device__ __forceinline__ void lstm_phase(const float* __restrict__ hsrc,
                                           const float* __restrict__ WT,
                                           const float* __restrict__ addv, int t,
                                           float* __restrict__ hdst,
                                           int mb0, int ntile,
                                           float* hsT, float* Ws) {
    const int tid = threadIdx.x;
    const int lane = tid & 31, wid = tid >> 5;
    ull acc0 = 0, acc1 = 0, acc2v = 0, acc3 = 0;

    for (int kb = 0; kb < H_; kb += 32) {
        {
            int k = tid & 31, mq = tid >> 5;
            #pragma unroll
            for (int i = 0; i < 4; i++)
                hsT[k*33 + mq + i*8] = hsrc[(mb0 + mq + i*8)*H_ + kb + k];
            int cc = tid & 63, kq = tid >> 6;
            int w2 = cc >> 3, g = (cc & 7) >> 1, du = cc & 1;
            int nglob = g*H_ + ntile*16 + w2*2 + du;
            #pragma unroll
            for (int i = 0; i < 8; i++)
                Ws[(kq*8 + i)*64 + cc] = WT[(size_t)(kb + kq*8 + i)*G4H_ + nglob];
        }
        __syncthreads();
        #pragma unroll
        for (int k = 0; k < 32; k++) {
            float hv = hsT[k*33 + lane];
            ull hp = pack2(hv, hv);
            const ulonglong2* wp = (const ulonglong2*)(Ws + k*64 + wid*8);
            ulonglong2 wA = wp[0], wB = wp[1];
            fma2(acc0, hp, wA.x);   // gate i (2 units)
            fma2(acc1, hp, wA.y);   // gate f
            fma2(acc2v, hp, wB.x);  // gate g
            fma2(acc3, hp, wB.y);   // gate o
        }
        __syncthreads();
    }

    int b = mb0 + lane;
    float2 gi = unpack2(acc0), gf = unpack2(acc1), gg = unpack2(acc2v), go = unpack2(acc3);
    const float* av = USE_X0 ? (addv + ((size_t)b*T_ + t)*G4H_) : addv;
    #pragma unroll
    for (int du = 0; du < 2; du++) {
        int u = ntile*16 + wid*2 + du;
        float vi = (du ? gi.y : gi.x) + av[0*H_ + u];
        float vf = (du ? gf.y : gf.x) + av[1*H_ + u];
        float vg = (du ? gg.y : gg.x) + av[2*H_ + u];
        float vo = (du ? go.y : go.x) + av[3*H_ + u];
        float co = g_c[b*H_ + u];
        float cn = sigf(vf)*co + sigf(vi)*tanhf(vg);
        g_c[b*H_ + u] = cn;
        hdst[b*H_ + u] = sigf(vo)*tanhf(cn);
    }
}

__global__ void __launch_bounds__(256, 1) lstm_kernel() {
    __shared__ float hsT[32*33];
    __shared__ float Ws [32*64];
    const int cta = blockIdx.x;
    const int mtile = cta >> 5, ntile = cta & 31;
    const int mb0 = mtile * 32;

    // zero owned h/c slice
    for (int i = threadIdx.x; i < 32*16; i += 256) {
        int m = i >> 4, u = i & 15;
        int idx = (mb0 + m)*H_ + ntile*16 + u;
        g_h[idx] = 0.0f;
        g_c[idx] = 0.0f;
    }
    gsync();

    for (int t = 0; t < T_; t++) {
        // layer 0: gates = h@Whh0^T + X0[:,t]   (X0 already holds x@Wih0^T + biases)
        lstm_phase<true >(g_h,  g_WT_hh0, g_X0, t, g_h0, mb0, ntile, hsT, Ws);
        gsync();
        // layer 1 (x == h): gates = h0@(Wih1+Whh1)^T + b1
        lstm_phase<false>(g_h0, g_WT_1,   g_b1, t, g_h,  mb0, ntile, hsT, Ws);
        gsync();
    }
}

// ---------------- output heads ----------------
__global__ void __launch_bounds__(512) output_kernel(const float* __restrict__ W_out,
                                                     const float* __restrict__ b_out,
                                                     const float* __restrict__ W_cls,
                                                     const float* __restrict__ b_cls,
                                                     float* __restrict__ out) {
    __shared__ float hb[H_];
    int b = blockIdx.x, tid = threadIdx.x;
    hb[tid] = g_h[b*H_ + tid];
    __syncthreads();

    // cls_out: (b, kk, cc) -> out[12288 + b*512 + tid]
    int kk = tid >> 4, cc = tid & 15;
    float acc = 0.0f;
    #pragma unroll 8
    for (int k = 0; k < H_; k++)
        acc = fmaf(hb[k], W_cls[(size_t)kk*H_*CARD_ + k*CARD_ + cc], acc);
    out[12288 + b*512 + tid] = acc + b_cls[tid];

    // cont_out: (b, j<96) -> out[b*96 + j]
    if (tid < NCONT_) {
        float a2 = 0.0f;
        #pragma unroll 8
        for (int k = 0; k < H_; k++)
            a2 = fmaf(hb[k], W_out[k*NCONT_ + tid], a2);
        out[b*NCONT_ + tid] = a2 + b_out[tid];
    }

    // h, c passthrough
    out[77824  + b*512 + tid] = hb[tid];
    out[143360 + b*512 + tid] = g_c[b*H_ + tid];
}

// ---------------- entry ----------------
extern "C" void kernel_launch(void* const* d_in, const int* in_sizes, int n_in,
                              void* d_out, int out_size) {
    (void)in_sizes; (void)n_in; (void)out_size;
    const int*   unscaled = (const int*)  d_in[0];
    const float* scaled   = (const float*)d_in[1];
    const float* emb      = (const float*)d_in[2];
    const float* W_in     = (const float*)d_in[3];
    const float* b_in     = (const float*)d_in[4];
    const float* Wih0     = (const float*)d_in[5];
    const float* Whh0     = (const float*)d_in[6];
    const float* bih0     = (const float*)d_in[7];
    const float* bhh0     = (const float*)d_in[8];
    const float* Wih1     = (const float*)d_in[9];
    const float* Whh1     = (const float*)d_in[10];
    const float* bih1     = (const float*)d_in[11];
    const float* bhh1     = (const float*)d_in[12];
    const float* W_out    = (const float*)d_in[13];
    const float* b_out    = (const float*)d_in[14];
    const float* W_cls    = (const float*)d_in[15];
    const float* b_cls    = (const float*)d_in[16];
    float* out = (float*)d_out;

    prep_kernel<<<G4H_, H_>>>(Wih0, Whh0, Wih1, Whh1, bih0, bhh0, bih1, bhh1);
    build_xin_kernel<<<BT_, INPUT_LEN_>>>(unscaled, scaled, emb);
    gemm1_kernel<<<dim3(BT_/128, H_/64),   256>>>(W_in, b_in);
    gemm2_kernel<<<dim3(BT_/128, G4H_/64), 256>>>();
    lstm_kernel<<<NBLK_, 256>>>();
    output_kernel<<<B_, 512>>>(W_out, b_out, W_cls, b_cls, out);
}

// round 3
// speedup vs baseline: 1.2129x; 1.2129x over previous
#include <cuda_runtime.h>
#include <cstdint>

#define B_ 128
#define T_ 256
#define F_ 128
#define NCAT_ 32
#define CARD_ 16
#define E_ 8
#define H_ 512
#define INPUT_LEN_ 352
#define NCONT_ 96
#define BT_ (B_*T_)
#define G4H_ 2048
#define NBLK_ 128   // persistent grid size

typedef unsigned long long ull;

// ---------------- scratch (device globals: allocation-free rule) ----------------
__device__ float g_xin[(size_t)BT_*INPUT_LEN_];   // 46 MB
__device__ float g_x  [(size_t)BT_*H_];           // 67 MB
__device__ float g_X0 [(size_t)BT_*G4H_];         // 268 MB: x@Wih0^T + bih0 + bhh0
__device__ float g_WT_ih0[H_*G4H_];               // [k][n] transpose for gemm2
__device__ float g_Wp0[H_*G4H_];                  // Whh0 permuted: [ntile][k][cc]
__device__ float g_Wp1[H_*G4H_];                  // (Wih1+Whh1) permuted: [ntile][k][cc]
__device__ float g_b0[G4H_];                      // bih0+bhh0 (folded into X0)
__device__ float g_b1[G4H_];                      // bih1+bhh1
__device__ float g_h [B_*H_];
__device__ float g_h0[B_*H_];
__device__ float g_c [B_*H_];
__device__ unsigned g_bar_count = 0;
__device__ unsigned g_bar_gen   = 0;

// ---------------- helpers ----------------
__device__ __forceinline__ ull pack2(float x, float y) {
    ull r; asm("mov.b64 %0, {%1, %2};" : "=l"(r) : "f"(x), "f"(y)); return r;
}
__device__ __forceinline__ float2 unpack2(ull v) {
    float2 r; asm("mov.b64 {%0, %1}, %2;" : "=f"(r.x), "=f"(r.y) : "l"(v)); return r;
}
// packed dual-FMA: d = a*b + d  (two f32 lanes per instruction)
__device__ __forceinline__ void fma2(ull& d, ull a, ull b) {
    asm("fma.rn.f32x2 %0, %1, %2, %0;" : "+l"(d) : "l"(a), "l"(b));
}
__device__ __forceinline__ float sigf(float x) { return 1.0f / (1.0f + __expf(-x)); }

// grid-wide barrier (all NBLK_ CTAs co-resident: grid <= SM count, 1 CTA/SM)
__device__ __forceinline__ void gsync() {
    __syncthreads();
    if (threadIdx.x == 0) {
        volatile unsigned* genp = &g_bar_gen;
        unsigned gen = *genp;
        __threadfence();
        unsigned t = atomicAdd(&g_bar_count, 1u);
        if (t == (unsigned)NBLK_ - 1u) {
            atomicExch(&g_bar_count, 0u);
            __threadfence();
            atomicAdd(&g_bar_gen, 1u);
        } else {
            while (*genp == gen) { __nanosleep(32); }
        }
        __threadfence();
    }
    __syncthreads();
}

// ---------------- prep: weight transposes/permutes + bias sums ----------------
// Permuted layout: for gate-row n = g*H + u, with u = ntile*16 + w2*2 + du:
//   cc = w2*8 + g*2 + du;  g_Wp[((ntile*512 + k)*64) + cc] = W[n*H + k]
// This makes the LSTM's per-kb weight fill a contiguous slab copy.
__global__ void prep_kernel(const float* __restrict__ Wih0, const float* __restrict__ Whh0,
                            const float* __restrict__ Wih1, const float* __restrict__ Whh1,
                            const float* __restrict__ bih0, const float* __restrict__ bhh0,
                            const float* __restrict__ bih1, const float* __restrict__ bhh1) {
    int n = blockIdx.x;      // 0..2047 (gate-row)
    int k = threadIdx.x;     // 0..511
    float wih0 = Wih0[n*H_ + k];
    float whh0 = Whh0[n*H_ + k];
    float w1   = Wih1[n*H_ + k] + Whh1[n*H_ + k];

    g_WT_ih0[k*G4H_ + n] = wih0;

    int g  = n >> 9;
    int u  = n & 511;
    int ntile = u >> 4;
    int w2 = (u & 15) >> 1;
    int du = u & 1;
    int cc = w2*8 + g*2 + du;
    size_t idx = ((size_t)(ntile*H_ + k))*64 + cc;
    g_Wp0[idx] = whh0;
    g_Wp1[idx] = w1;

    if (k == 0) {
        g_b0[n] = bih0[n] + bhh0[n];
        g_b1[n] = bih1[n] + bhh1[n];
    }
}

// ---------------- build xin: embedding gather + cont interleave ----------------
__global__ void build_xin_kernel(const int* __restrict__ unscaled,
                                 const float* __restrict__ scaled,
                                 const float* __restrict__ emb) {
    int bt = blockIdx.x;
    int i  = threadIdx.x;             // 0..351
    int k  = i / 11;                  // categorical group
    int j  = i - k*11;                // 0..7 emb, 8..10 cont
    float v;
    if (j < 8) {
        int cid = unscaled[(size_t)bt*F_ + 4*k];
        v = emb[(k*CARD_ + cid)*E_ + j];
    } else {
        v = scaled[(size_t)bt*F_ + 4*k + (j - 8) + 1];
    }
    g_xin[(size_t)bt*INPUT_LEN_ + i] = v;
}

// ---------------- generic fp32x2 tiled GEMM: C = act(A[M,K] @ W[K,N] + bias) ----------------
// tile: 128m x 64n x 32k, 256 threads, 4m x 8n per thread
template<bool RELU>
__device__ __forceinline__ void gemm_core(const float* __restrict__ A,
                                          const float* __restrict__ Wg,
                                          const float* __restrict__ bias,
                                          float* __restrict__ C, int K, int N) {
    __shared__ float AsT[32*132];   // [k][m]
    __shared__ float Ws [32*64];    // [k][n]
    const int m0 = blockIdx.x * 128;
    const int n0 = blockIdx.y * 64;
    const int tid = threadIdx.x, lane = tid & 31, wid = tid >> 5;
    ull acc[4][4];
    #pragma unroll
    for (int a = 0; a < 4; a++)
        #pragma unroll
        for (int b = 0; b < 4; b++) acc[a][b] = 0ull;

    for (int kb = 0; kb < K; kb += 32) {
        {
            int k = tid & 31, mq = tid >> 5;
            #pragma unroll
            for (int i = 0; i < 16; i++)
                AsT[k*132 + mq + i*8] = A[(size_t)(m0 + mq + i*8)*K + kb + k];
            int n = tid & 63, kq = tid >> 6;
            #pragma unroll
            for (int i = 0; i < 8; i++)
                Ws[(kq*8 + i)*64 + n] = Wg[(size_t)(kb + kq*8 + i)*N + n0 + n];
        }
        __syncthreads();
        #pragma unroll
        for (int kk = 0; kk < 32; kk++) {
            float4 a4 = *(const float4*)(AsT + kk*132 + lane*4);
            const ulonglong2* wp = (const ulonglong2*)(Ws + kk*64 + wid*8);
            ulonglong2 wA = wp[0], wB = wp[1];
            float am[4] = {a4.x, a4.y, a4.z, a4.w};
            #pragma unroll
            for (int mi = 0; mi < 4; mi++) {
                ull ap = pack2(am[mi], am[mi]);
                fma2(acc[mi][0], ap, wA.x);
                fma2(acc[mi][1], ap, wA.y);
                fma2(acc[mi][2], ap, wB.x);
                fma2(acc[mi][3], ap, wB.y);
            }
        }
        __syncthreads();
    }
    const int nb = n0 + wid*8;
    float bv[8];
    #pragma unroll
    for (int j = 0; j < 8; j++) bv[j] = bias[nb + j];
    #pragma unroll
    for (int mi = 0; mi < 4; mi++) {
        int row = m0 + lane*4 + mi;
        float* crow = C + (size_t)row*N + nb;
        #pragma unroll
        for (int p = 0; p < 4; p++) {
            float2 v = unpack2(acc[mi][p]);
            v.x += bv[2*p]; v.y += bv[2*p + 1];
            if (RELU) { v.x = fmaxf(v.x, 0.0f); v.y = fmaxf(v.y, 0.0f); }
            *(float2*)(crow + 2*p) = v;
        }
    }
}

__global__ void __launch_bounds__(256) gemm1_kernel(const float* __restrict__ W_in,
                                                    const float* __restrict__ b_in) {
    gemm_core<true>(g_xin, W_in, b_in, g_x, INPUT_LEN_, H_);     // x = relu(xin@W_in+b)
}
__global__ void __launch_bounds__(256) gemm2_kernel() {
    gemm_core<false>(g_x, g_WT_ih0, g_b0, g_X0, H_, G4H_);       // X0 = x@Wih0^T + b0
}

// ---------------- persistent LSTM ----------------
// CTA (mtile, ntile): batches mtile*32..+31, hidden units ntile*16..+15, all 4 gates.
// Weights are pre-permuted so the per-kb fill is a contiguous 8KB slab copy.
// Register double-buffering hides the L2 latency under the fp32x2 math.
template<bool USE_X0>
__device__ __forceinline__ void lstm_phase(const float* __restrict__ hsrc,
                                           const float* __restrict__ Wp,   // ntile slice base
                                           const float* __restrict__ addv, int t,
                                           float* __restrict__ hdst,
                                           int mb0, int ntile,
                                           float* hsT, float* Ws) {
    const int tid = threadIdx.x;
    const int lane = tid & 31, wid = tid >> 5;
    const int kf = tid & 31, mq = tid >> 5;
    ull acc0 = 0, acc1 = 0, acc2v = 0, acc3 = 0;

    float4 wa, wb;
    float hr[4];
    // prefetch kb = 0
    {
        const float4* p = (const float4*)(Wp);
        wa = p[tid]; wb = p[tid + 256];
        #pragma unroll
        for (int i = 0; i < 4; i++)
            hr[i] = hsrc[(mb0 + mq + i*8)*H_ + kf];
    }

    for (int kb = 0; kb < H_; kb += 32) {
        // stage to smem
        ((float4*)Ws)[tid] = wa;
        ((float4*)Ws)[tid + 256] = wb;
        #pragma unroll
        for (int i = 0; i < 4; i++)
            hsT[kf*33 + mq + i*8] = hr[i];
        __syncthreads();
        // prefetch next kb
        if (kb + 32 < H_) {
            const float4* p = (const float4*)(Wp + (size_t)(kb + 32)*64);
            wa = p[tid]; wb = p[tid + 256];
            #pragma unroll
            for (int i = 0; i < 4; i++)
                hr[i] = hsrc[(mb0 + mq + i*8)*H_ + kb + 32 + kf];
        }
        #pragma unroll
        for (int k = 0; k < 32; k++) {
            float hv = hsT[k*33 + lane];
            ull hp = pack2(hv, hv);
            const ulonglong2* wpn = (const ulonglong2*)(Ws + k*64 + wid*8);
            ulonglong2 wA = wpn[0], wB = wpn[1];
            fma2(acc0, hp, wA.x);   // gate i (2 units)
            fma2(acc1, hp, wA.y);   // gate f
            fma2(acc2v, hp, wB.x);  // gate g
            fma2(acc3, hp, wB.y);   // gate o
        }
        __syncthreads();
    }

    int b = mb0 + lane;
    float2 gi = unpack2(acc0), gf = unpack2(acc1), gg = unpack2(acc2v), go = unpack2(acc3);
    const float* av = USE_X0 ? (addv + ((size_t)b*T_ + t)*G4H_) : addv;
    #pragma unroll
    for (int du = 0; du < 2; du++) {
        int u = ntile*16 + wid*2 + du;
        float vi = (du ? gi.y : gi.x) + av[0*H_ + u];
        float vf = (du ? gf.y : gf.x) + av[1*H_ + u];
        float vg = (du ? gg.y : gg.x) + av[2*H_ + u];
        float vo = (du ? go.y : go.x) + av[3*H_ + u];
        float co = g_c[b*H_ + u];
        float cn = sigf(vf)*co + sigf(vi)*tanhf(vg);
        g_c[b*H_ + u] = cn;
        hdst[b*H_ + u] = sigf(vo)*tanhf(cn);
    }
}

__global__ void __launch_bounds__(256, 1) lstm_kernel() {
    __shared__ float hsT[32*33];
    __shared__ float Ws [32*64];
    const int cta = blockIdx.x;
    const int mtile = cta >> 5, ntile = cta & 31;
    const int mb0 = mtile * 32;
    const float* Wp0 = g_Wp0 + (size_t)ntile*H_*64;
    const float* Wp1 = g_Wp1 + (size_t)ntile*H_*64;

    // zero owned h/c slice
    for (int i = threadIdx.x; i < 32*16; i += 256) {
        int m = i >> 4, u = i & 15;
        int idx = (mb0 + m)*H_ + ntile*16 + u;
        g_h[idx] = 0.0f;
        g_c[idx] = 0.0f;
    }
    gsync();

    for (int t = 0; t < T_; t++) {
        // layer 0: gates = h@Whh0^T + X0[:,t]   (X0 already holds x@Wih0^T + biases)
        lstm_phase<true >(g_h,  Wp0, g_X0, t, g_h0, mb0, ntile, hsT, Ws);
        gsync();
        // layer 1 (x == h): gates = h0@(Wih1+Whh1)^T + b1
        lstm_phase<false>(g_h0, Wp1, g_b1, t, g_h,  mb0, ntile, hsT, Ws);
        gsync();
    }
}

// ---------------- output heads ----------------
__global__ void __launch_bounds__(512) output_kernel(const float* __restrict__ W_out,
                                                     const float* __restrict__ b_out,
                                                     const float* __restrict__ W_cls,
                                                     const float* __restrict__ b_cls,
                                                     float* __restrict__ out) {
    __shared__ float hb[H_];
    int b = blockIdx.x, tid = threadIdx.x;
    hb[tid] = g_h[b*H_ + tid];
    __syncthreads();

    // cls_out: (b, kk, cc) -> out[12288 + b*512 + tid]
    int kk = tid >> 4, cc = tid & 15;
    float acc = 0.0f;
    #pragma unroll 8
    for (int k = 0; k < H_; k++)
        acc = fmaf(hb[k], W_cls[(size_t)kk*H_*CARD_ + k*CARD_ + cc], acc);
    out[12288 + b*512 + tid] = acc + b_cls[tid];

    // cont_out: (b, j<96) -> out[b*96 + j]
    if (tid < NCONT_) {
        float a2 = 0.0f;
        #pragma unroll 8
        for (int k = 0; k < H_; k++)
            a2 = fmaf(hb[k], W_out[k*NCONT_ + tid], a2);
        out[b*NCONT_ + tid] = a2 + b_out[tid];
    }

    // h, c passthrough
    out[77824  + b*512 + tid] = hb[tid];
    out[143360 + b*512 + tid] = g_c[b*H_ + tid];
}

// ---------------- entry ----------------
extern "C" void kernel_launch(void* const* d_in, const int* in_sizes, int n_in,
                              void* d_out, int out_size) {
    (void)in_sizes; (void)n_in; (void)out_size;
    const int*   unscaled = (const int*)  d_in[0];
    const float* scaled   = (const float*)d_in[1];
    const float* emb      = (const float*)d_in[2];
    const float* W_in     = (const float*)d_in[3];
    const float* b_in     = (const float*)d_in[4];
    const float* Wih0     = (const float*)d_in[5];
    const float* Whh0     = (const float*)d_in[6];
    const float* bih0     = (const float*)d_in[7];
    const float* bhh0     = (const float*)d_in[8];
    const float* Wih1     = (const float*)d_in[9];
    const float* Whh1     = (const float*)d_in[10];
    const float* bih1     = (const float*)d_in[11];
    const float* bhh1     = (const float*)d_in[12];
    const float* W_out    = (const float*)d_in[13];
    const float* b_out    = (const float*)d_in[14];
    const float* W_cls    = (const float*)d_in[15];
    const float* b_cls    = (const float*)d_in[16];
    float* out = (float*)d_out;

    prep_kernel<<<G4H_, H_>>>(Wih0, Whh0, Wih1, Whh1, bih0, bhh0, bih1, bhh1);
    build_xin_kernel<<<BT_, INPUT_LEN_>>>(unscaled, scaled, emb);
    gemm1_kernel<<<dim3(BT_/128, H_/64),   256>>>(W_in, b_in);
    gemm2_kernel<<<dim3(BT_/128, G4H_/64), 256>>>();
    lstm_kernel<<<NBLK_, 256>>>();
    output_kernel<<<B_, 512>>>(W_out, b_out, W_cls, b_cls, out);
}

// round 5
// speedup vs baseline: 2.1151x; 1.7439x over previous
#include <cuda_runtime.h>
#include <cuda_fp16.h>
#include <cstdint>

#define B_ 128
#define T_ 256
#define F_ 128
#define NCAT_ 32
#define CARD_ 16
#define E_ 8
#define H_ 512
#define INPUT_LEN_ 352
#define NCONT_ 96
#define BT_ (B_*T_)
#define G4H_ 2048
#define NBLK_ 128          // LSTM persistent grid (1 CTA per unit-group)
#define LSTM_THREADS 128
#define WSTRIDE 520        // padded k-stride (halves) for bank-conflict-free LDS
#define IMG_HALVES (16*WSTRIDE)        // one weight image: 16 n-rows x 520
#define CTA_IMG_HALVES (4*IMG_HALVES)  // 4 images per CTA (L0hi,L0lo,L1hi,L1lo)

typedef unsigned long long ull;

// ---------------- scratch (device globals) ----------------
__device__ float g_xin[(size_t)BT_*INPUT_LEN_];
__device__ float g_x  [(size_t)BT_*H_];
__device__ float g_X0 [(size_t)BT_*G4H_];          // x@Wih0^T + bih0 + bhh0
__device__ float g_WT_ih0[H_*G4H_];
__device__ float g_b0[G4H_];
__device__ float g_b1[G4H_];
__device__ __half g_img[(size_t)NBLK_*CTA_IMG_HALVES];  // per-CTA weight images, ~8.5MB
__device__ __half g_h16A[B_*H_];   // h0 (layer0 output)
__device__ __half g_h16B[B_*H_];   // h  (layer1 output)
__device__ float g_h [B_*H_];
__device__ float g_c [B_*H_];
__device__ unsigned g_bar_count = 0;
__device__ unsigned g_bar_gen   = 0;

// ---------------- helpers ----------------
__device__ __forceinline__ float sigf(float x) { return 1.0f / (1.0f + __expf(-x)); }
__device__ __forceinline__ ull pack2(float x, float y) {
    ull r; asm("mov.b64 %0, {%1, %2};" : "=l"(r) : "f"(x), "f"(y)); return r;
}
__device__ __forceinline__ float2 unpack2(ull v) {
    float2 r; asm("mov.b64 {%0, %1}, %2;" : "=f"(r.x), "=f"(r.y) : "l"(v)); return r;
}
__device__ __forceinline__ void fma2(ull& d, ull a, ull b) {
    asm("fma.rn.f32x2 %0, %1, %2, %0;" : "+l"(d) : "l"(a), "l"(b));
}
// HMMA m16n8k16 row.col f16*f16 -> f32
__device__ __forceinline__ void mma16816(float* d, const uint32_t* a, const uint32_t* b) {
    asm volatile("mma.sync.aligned.m16n8k16.row.col.f32.f16.f16.f32 "
        "{%0,%1,%2,%3}, {%4,%5,%6,%7}, {%8,%9}, {%0,%1,%2,%3};"
        : "+f"(d[0]), "+f"(d[1]), "+f"(d[2]), "+f"(d[3])
        : "r"(a[0]), "r"(a[1]), "r"(a[2]), "r"(a[3]), "r"(b[0]), "r"(b[1]));
}

// grid-wide barrier (NBLK_ CTAs co-resident, 1 small CTA/SM)
__device__ __forceinline__ void gsync() {
    __syncthreads();
    if (threadIdx.x == 0) {
        volatile unsigned* genp = &g_bar_gen;
        unsigned gen = *genp;
        __threadfence();
        unsigned t = atomicAdd(&g_bar_count, 1u);
        if (t == (unsigned)NBLK_ - 1u) {
            atomicExch(&g_bar_count, 0u);
            __threadfence();
            atomicAdd(&g_bar_gen, 1u);
        } else {
            while (*genp == gen) { __nanosleep(32); }
        }
        __threadfence();
    }
    __syncthreads();
}

// ---------------- prep: weight images (fp16 hi/lo, [n][k] padded) + transposes ----------------
// gate-row n = g*512 + u;  u = ct*4 + q;  image n_local: g<2 -> 2q+g, else 2q+8+(g-2)
__global__ void prep_kernel(const float* __restrict__ Wih0, const float* __restrict__ Whh0,
                            const float* __restrict__ Wih1, const float* __restrict__ Whh1,
                            const float* __restrict__ bih0, const float* __restrict__ bhh0,
                            const float* __restrict__ bih1, const float* __restrict__ bhh1) {
    int n = blockIdx.x;      // 0..2047
    int k = threadIdx.x;     // 0..511
    float wih0 = Wih0[n*H_ + k];
    float whh0 = Whh0[n*H_ + k];
    float w1   = Wih1[n*H_ + k] + Whh1[n*H_ + k];

    g_WT_ih0[k*G4H_ + n] = wih0;

    int g = n >> 9, u = n & 511;
    int ct = u >> 2, q = u & 3;
    int n_local = (g < 2) ? (2*q + g) : (2*q + 8 + (g - 2));
    size_t base = (size_t)ct * CTA_IMG_HALVES + (size_t)n_local * WSTRIDE + k;

    __half h0hi = __float2half(whh0);
    __half h0lo = __float2half((whh0 - __half2float(h0hi)) * 2048.0f);
    __half h1hi = __float2half(w1);
    __half h1lo = __float2half((w1 - __half2float(h1hi)) * 2048.0f);
    g_img[base + 0*IMG_HALVES] = h0hi;
    g_img[base + 1*IMG_HALVES] = h0lo;
    g_img[base + 2*IMG_HALVES] = h1hi;
    g_img[base + 3*IMG_HALVES] = h1lo;

    if (k == 0) {
        g_b0[n] = bih0[n] + bhh0[n];
        g_b1[n] = bih1[n] + bhh1[n];
    }
}

// ---------------- build xin ----------------
__global__ void build_xin_kernel(const int* __restrict__ unscaled,
                                 const float* __restrict__ scaled,
                                 const float* __restrict__ emb) {
    int bt = blockIdx.x;
    int i  = threadIdx.x;
    int k  = i / 11;
    int j  = i - k*11;
    float v;
    if (j < 8) {
        int cid = unscaled[(size_t)bt*F_ + 4*k];
        v = emb[(k*CARD_ + cid)*E_ + j];
    } else {
        v = scaled[(size_t)bt*F_ + 4*k + (j - 8) + 1];
    }
    g_xin[(size_t)bt*INPUT_LEN_ + i] = v;
}

// ---------------- fp32x2 tiled GEMM (prologue) ----------------
template<bool RELU>
__device__ __forceinline__ void gemm_core(const float* __restrict__ A,
                                          const float* __restrict__ Wg,
                                          const float* __restrict__ bias,
                                          float* __restrict__ C, int K, int N) {
    __shared__ float AsT[32*132];
    __shared__ float Ws [32*64];
    const int m0 = blockIdx.x * 128;
    const int n0 = blockIdx.y * 64;
    const int tid = threadIdx.x, lane = tid & 31, wid = tid >> 5;
    ull acc[4][4];
    #pragma unroll
    for (int a = 0; a < 4; a++)
        #pragma unroll
        for (int b = 0; b < 4; b++) acc[a][b] = 0ull;

    for (int kb = 0; kb < K; kb += 32) {
        {
            int k = tid & 31, mq = tid >> 5;
            #pragma unroll
            for (int i = 0; i < 16; i++)
                AsT[k*132 + mq + i*8] = A[(size_t)(m0 + mq + i*8)*K + kb + k];
            int n = tid & 63, kq = tid >> 6;
            #pragma unroll
            for (int i = 0; i < 8; i++)
                Ws[(kq*8 + i)*64 + n] = Wg[(size_t)(kb + kq*8 + i)*N + n0 + n];
        }
        __syncthreads();
        #pragma unroll
        for (int kk = 0; kk < 32; kk++) {
            float4 a4 = *(const float4*)(AsT + kk*132 + lane*4);
            const ulonglong2* wp = (const ulonglong2*)(Ws + kk*64 + wid*8);
            ulonglong2 wA = wp[0], wB = wp[1];
            float am[4] = {a4.x, a4.y, a4.z, a4.w};
            #pragma unroll
            for (int mi = 0; mi < 4; mi++) {
                ull ap = pack2(am[mi], am[mi]);
                fma2(acc[mi][0], ap, wA.x);
                fma2(acc[mi][1], ap, wA.y);
                fma2(acc[mi][2], ap, wB.x);
                fma2(acc[mi][3], ap, wB.y);
            }
        }
        __syncthreads();
    }
    const int nb = n0 + wid*8;
    float bv[8];
    #pragma unroll
    for (int j = 0; j < 8; j++) bv[j] = bias[nb + j];
    #pragma unroll
    for (int mi = 0; mi < 4; mi++) {
        int row = m0 + lane*4 + mi;
        float* crow = C + (size_t)row*N + nb;
        #pragma unroll
        for (int p = 0; p < 4; p++) {
            float2 v = unpack2(acc[mi][p]);
            v.x += bv[2*p]; v.y += bv[2*p + 1];
            if (RELU) { v.x = fmaxf(v.x, 0.0f); v.y = fmaxf(v.y, 0.0f); }
            *(float2*)(crow + 2*p) = v;
        }
    }
}

__global__ void __launch_bounds__(256) gemm1_kernel(const float* __restrict__ W_in,
                                                    const float* __restrict__ b_in) {
    gemm_core<true>(g_xin, W_in, b_in, g_x, INPUT_LEN_, H_);
}
__global__ void __launch_bounds__(256) gemm2_kernel() {
    gemm_core<false>(g_x, g_WT_ih0, g_b0, g_X0, H_, G4H_);
}

// ---------------- HMMA persistent LSTM ----------------
// CTA ct owns units [ct*4, ct*4+4), all 4 gates (N=16 image rows).
// Warp w owns batches [w*32, w*32+32) (2 m16 tiles). K=512, fp16 hi/lo weight split.
// Thread (lane) -> q=lane&3 (its unit), r=lane>>2. D pairs give all 4 gates of unit q.
template<int LAYER>
__device__ __forceinline__ void lstm_phase(int t, int ct, int w, int lane,
                                           const __half* __restrict__ hsrc,
                                           __half* __restrict__ hdst,
                                           const __half* __restrict__ sW,
                                           float* __restrict__ creg,
                                           const float* __restrict__ bb) {
    const int q = lane & 3, r = lane >> 2;
    float accH[2][2][4], accL[2][2][4];
    #pragma unroll
    for (int a = 0; a < 2; a++)
        #pragma unroll
        for (int b = 0; b < 2; b++)
            #pragma unroll
            for (int cdx = 0; cdx < 4; cdx++) { accH[a][b][cdx] = 0.f; accL[a][b][cdx] = 0.f; }

    const __half* ab  = hsrc + (size_t)(w*32 + r)*H_ + q*2;
    const __half* wHi = sW + (LAYER*2 + 0)*IMG_HALVES + r*WSTRIDE + q*2;
    const __half* wLo = sW + (LAYER*2 + 1)*IMG_HALVES + r*WSTRIDE + q*2;

    #pragma unroll 4
    for (int ks = 0; ks < 32; ks++) {
        const int k0 = ks*16;
        uint32_t a[2][4];
        #pragma unroll
        for (int mt = 0; mt < 2; mt++) {
            const __half* p = ab + mt*16*H_ + k0;
            a[mt][0] = *(const uint32_t*)(p);
            a[mt][1] = *(const uint32_t*)(p + 8*H_);
            a[mt][2] = *(const uint32_t*)(p + 8);
            a[mt][3] = *(const uint32_t*)(p + 8*H_ + 8);
        }
        uint32_t bh[2][2], bl[2][2];
        #pragma unroll
        for (int nt = 0; nt < 2; nt++) {
            const __half* ph = wHi + nt*8*WSTRIDE + k0;
            const __half* pl = wLo + nt*8*WSTRIDE + k0;
            bh[nt][0] = *(const uint32_t*)ph;       bh[nt][1] = *(const uint32_t*)(ph + 8);
            bl[nt][0] = *(const uint32_t*)pl;       bl[nt][1] = *(const uint32_t*)(pl + 8);
        }
        #pragma unroll
        for (int mt = 0; mt < 2; mt++)
            #pragma unroll
            for (int nt = 0; nt < 2; nt++) {
                mma16816(accH[mt][nt], a[mt], bh[nt]);
                mma16816(accL[mt][nt], a[mt], bl[nt]);
            }
    }

    const float s = 1.0f / 2048.0f;
    const int unit = ct*4 + q;
    #pragma unroll
    for (int mt = 0; mt < 2; mt++) {
        #pragma unroll
        for (int hr = 0; hr < 2; hr++) {
            int batch = w*32 + mt*16 + hr*8 + r;
            float vi = accH[mt][0][hr*2+0] + accL[mt][0][hr*2+0]*s;
            float vf = accH[mt][0][hr*2+1] + accL[mt][0][hr*2+1]*s;
            float vg = accH[mt][1][hr*2+0] + accL[mt][1][hr*2+0]*s;
            float vo = accH[mt][1][hr*2+1] + accL[mt][1][hr*2+1]*s;
            if (LAYER == 0) {
                const float* xb = g_X0 + ((size_t)batch*T_ + t)*G4H_ + unit;
                vi += xb[0]; vf += xb[512]; vg += xb[1024]; vo += xb[1536];
            } else {
                vi += bb[0]; vf += bb[1]; vg += bb[2]; vo += bb[3];
            }
            float c = creg[mt*2 + hr];
            float cn = sigf(vf)*c + sigf(vi)*tanhf(vg);
            creg[mt*2 + hr] = cn;
            float hv = sigf(vo)*tanhf(cn);
            hdst[(size_t)batch*H_ + unit] = __float2half_rn(hv);
            if (LAYER == 1 && t == T_-1) {
                g_h[batch*H_ + unit] = hv;
                g_c[batch*H_ + unit] = cn;
            }
        }
    }
}

__global__ void __launch_bounds__(LSTM_THREADS, 1) lstm_kernel() {
    extern __shared__ __half sW[];   // 4 * IMG_HALVES halves = 66560 B
    const int tid = threadIdx.x;
    const int w = tid >> 5, lane = tid & 31;
    const int ct = blockIdx.x;

    // copy resident weight images (66560 B)
    {
        const uint4* src = (const uint4*)(g_img + (size_t)ct*CTA_IMG_HALVES);
        uint4* dst = (uint4*)sW;
        #pragma unroll 4
        for (int i = tid; i < CTA_IMG_HALVES/8; i += LSTM_THREADS)
            dst[i] = src[i];
    }
    // layer1 biases for this thread's unit
    const int unit = ct*4 + (lane & 3);
    float bb[4];
    #pragma unroll
    for (int g = 0; g < 4; g++) bb[g] = g_b1[g*H_ + unit];

    // zero initial h16 slice (thread = batch, this CTA's 4 units)
    *(uint2*)(g_h16B + (size_t)tid*H_ + ct*4) = make_uint2(0u, 0u);

    __syncthreads();

    float creg[4] = {0.f, 0.f, 0.f, 0.f};

    gsync();   // all h16 slices visible

    for (int t = 0; t < T_; t++) {
        lstm_phase<0>(t, ct, w, lane, g_h16B, g_h16A, sW, creg, bb);
        gsync();
        lstm_phase<1>(t, ct, w, lane, g_h16A, g_h16B, sW, creg, bb);
        gsync();
    }
}

// ---------------- output heads ----------------
__global__ void __launch_bounds__(512) output_kernel(const float* __restrict__ W_out,
                                                     const float* __restrict__ b_out,
                                                     const float* __restrict__ W_cls,
                                                     const float* __restrict__ b_cls,
                                                     float* __restrict__ out) {
    __shared__ float hb[H_];
    int b = blockIdx.x, tid = threadIdx.x;
    hb[tid] = g_h[b*H_ + tid];
    __syncthreads();

    int kk = tid >> 4, cc = tid & 15;
    float acc = 0.0f;
    #pragma unroll 8
    for (int k = 0; k < H_; k++)
        acc = fmaf(hb[k], W_cls[(size_t)kk*H_*CARD_ + k*CARD_ + cc], acc);
    out[12288 + b*512 + tid] = acc + b_cls[tid];

    if (tid < NCONT_) {
        float a2 = 0.0f;
        #pragma unroll 8
        for (int k = 0; k < H_; k++)
            a2 = fmaf(hb[k], W_out[k*NCONT_ + tid], a2);
        out[b*NCONT_ + tid] = a2 + b_out[tid];
    }
    out[77824  + b*512 + tid] = hb[tid];
    out[143360 + b*512 + tid] = g_c[b*H_ + tid];
}

// ---------------- entry ----------------
extern "C" void kernel_launch(void* const* d_in, const int* in_sizes, int n_in,
                              void* d_out, int out_size) {
    (void)in_sizes; (void)n_in; (void)out_size;
    const int*   unscaled = (const int*)  d_in[0];
    const float* scaled   = (const float*)d_in[1];
    const float* emb      = (const float*)d_in[2];
    const float* W_in     = (const float*)d_in[3];
    const float* b_in     = (const float*)d_in[4];
    const float* Wih0     = (const float*)d_in[5];
    const float* Whh0     = (const float*)d_in[6];
    const float* bih0     = (const float*)d_in[7];
    const float* bhh0     = (const float*)d_in[8];
    const float* Wih1     = (const float*)d_in[9];
    const float* Whh1     = (const float*)d_in[10];
    const float* bih1     = (const float*)d_in[11];
    const float* bhh1     = (const float*)d_in[12];
    const float* W_out    = (const float*)d_in[13];
    const float* b_out    = (const float*)d_in[14];
    const float* W_cls    = (const float*)d_in[15];
    const float* b_cls    = (const float*)d_in[16];
    float* out = (float*)d_out;

    static bool attr_set = false;
    if (!attr_set) {
        cudaFuncSetAttribute(lstm_kernel, cudaFuncAttributeMaxDynamicSharedMemorySize,
                             (int)(CTA_IMG_HALVES*sizeof(__half)));
        attr_set = true;
    }

    prep_kernel<<<G4H_, H_>>>(Wih0, Whh0, Wih1, Whh1, bih0, bhh0, bih1, bhh1);
    build_xin_kernel<<<BT_, INPUT_LEN_>>>(unscaled, scaled, emb);
    gemm1_kernel<<<dim3(BT_/128, H_/64),   256>>>(W_in, b_in);
    gemm2_kernel<<<dim3(BT_/128, G4H_/64), 256>>>();
    lstm_kernel<<<NBLK_, LSTM_THREADS, CTA_IMG_HALVES*sizeof(__half)>>>();
    output_kernel<<<B_, 512>>>(W_out, b_out, W_cls, b_cls, out);
}

// round 6
// speedup vs baseline: 4.3139x; 2.0395x over previous
#include <cuda_runtime.h>
#include <cuda_fp16.h>
#include <cstdint>

#define B_ 128
#define T_ 256
#define F_ 128
#define NCAT_ 32
#define CARD_ 16
#define E_ 8
#define H_ 512
#define INPUT_LEN_ 352
#define NCONT_ 96
#define BT_ (B_*T_)
#define G4H_ 2048
#define NBLK_ 128          // LSTM persistent grid
#define LSTM_THREADS 128
#define WSTRIDE 520        // padded k-stride (halves) for conflict-free weight LDS
#define IMG_HALVES (16*WSTRIDE)
#define CTA_IMG_HALVES (4*IMG_HALVES)

typedef unsigned long long ull;

// ---------------- scratch (device globals) ----------------
__device__ float  g_xin[(size_t)BT_*INPUT_LEN_];
__device__ __half g_x16h[(size_t)BT_*H_];
__device__ __half g_x16l[(size_t)BT_*H_];
__device__ float  g_X0 [(size_t)BT_*G4H_];         // x@Wih0^T + bih0 + bhh0
__device__ __half g_W16h[(size_t)G4H_*H_];         // Wih0 fp16 hi, [n][k]
__device__ __half g_W16l[(size_t)G4H_*H_];         // Wih0 residual*2048
__device__ float  g_b0[G4H_];
__device__ float  g_b1[G4H_];
__device__ __half g_img[(size_t)NBLK_*CTA_IMG_HALVES];  // LSTM per-CTA weight images
__device__ __half g_h16A[B_*H_];   // h0 (layer0 output)
__device__ __half g_h16B[B_*H_];   // h  (layer1 output)
__device__ float  g_h [B_*H_];
__device__ float  g_c [B_*H_];
__device__ unsigned g_bar_count = 0;
__device__ unsigned g_bar_gen   = 0;

// ---------------- helpers ----------------
__device__ __forceinline__ float sigf(float x) { return 1.0f / (1.0f + __expf(-x)); }
__device__ __forceinline__ ull pack2(float x, float y) {
    ull r; asm("mov.b64 %0, {%1, %2};" : "=l"(r) : "f"(x), "f"(y)); return r;
}
__device__ __forceinline__ float2 unpack2(ull v) {
    float2 r; asm("mov.b64 {%0, %1}, %2;" : "=f"(r.x), "=f"(r.y) : "l"(v)); return r;
}
__device__ __forceinline__ void fma2(ull& d, ull a, ull b) {
    asm("fma.rn.f32x2 %0, %1, %2, %0;" : "+l"(d) : "l"(a), "l"(b));
}
__device__ __forceinline__ uint32_t smem_u32(const void* p) {
    uint32_t a;
    asm("{ .reg .u64 t; cvta.to.shared.u64 t, %1; cvt.u32.u64 %0, t; }" : "=r"(a) : "l"(p));
    return a;
}
__device__ __forceinline__ void mma_f32(float* d, const uint32_t* a, const uint32_t* b) {
    asm volatile("mma.sync.aligned.m16n8k16.row.col.f32.f16.f16.f32 "
        "{%0,%1,%2,%3}, {%4,%5,%6,%7}, {%8,%9}, {%0,%1,%2,%3};"
        : "+f"(d[0]), "+f"(d[1]), "+f"(d[2]), "+f"(d[3])
        : "r"(a[0]), "r"(a[1]), "r"(a[2]), "r"(a[3]), "r"(b[0]), "r"(b[1]));
}
__device__ __forceinline__ void mma_f16acc(uint32_t* d, const uint32_t* a, const uint32_t* b) {
    asm volatile("mma.sync.aligned.m16n8k16.row.col.f16.f16.f16.f16 "
        "{%0,%1}, {%2,%3,%4,%5}, {%6,%7}, {%0,%1};"
        : "+r"(d[0]), "+r"(d[1])
        : "r"(a[0]), "r"(a[1]), "r"(a[2]), "r"(a[3]), "r"(b[0]), "r"(b[1]));
}
#define CP_ASYNC16(dst_u32, src_ptr) \
    asm volatile("cp.async.cg.shared.global [%0], [%1], 16;" :: "r"(dst_u32), "l"(src_ptr) : "memory")
#define CP_COMMIT() asm volatile("cp.async.commit_group;" ::: "memory")
#define CP_WAIT(n)  asm volatile("cp.async.wait_group %0;" :: "n"(n) : "memory")
#define LDSM_X4(r0,r1,r2,r3, a) \
    asm volatile("ldmatrix.sync.aligned.m8n8.x4.shared.b16 {%0,%1,%2,%3}, [%4];" \
        : "=r"(r0), "=r"(r1), "=r"(r2), "=r"(r3) : "r"(a))

// grid-wide barrier (NBLK_ CTAs co-resident, 1 CTA/SM)
__device__ __forceinline__ void gsync() {
    __syncthreads();
    if (threadIdx.x == 0) {
        volatile unsigned* genp = &g_bar_gen;
        unsigned gen = *genp;
        __threadfence();
        unsigned t = atomicAdd(&g_bar_count, 1u);
        if (t == (unsigned)NBLK_ - 1u) {
            atomicExch(&g_bar_count, 0u);
            __threadfence();
            atomicAdd(&g_bar_gen, 1u);
        } else {
            while (*genp == gen) { __nanosleep(32); }
        }
        __threadfence();
    }
    __syncthreads();
}

// ---------------- prep ----------------
__global__ void prep_kernel(const float* __restrict__ Wih0, const float* __restrict__ Whh0,
                            const float* __restrict__ Wih1, const float* __restrict__ Whh1,
                            const float* __restrict__ bih0, const float* __restrict__ bhh0,
                            const float* __restrict__ bih1, const float* __restrict__ bhh1) {
    int n = blockIdx.x;      // 0..2047
    int k = threadIdx.x;     // 0..511
    float wih0 = Wih0[n*H_ + k];
    float whh0 = Whh0[n*H_ + k];
    float w1   = Wih1[n*H_ + k] + Whh1[n*H_ + k];

    // gemm2 B operand (native [n][k]) hi/lo
    __half wh = __float2half_rn(wih0);
    g_W16h[(size_t)n*H_ + k] = wh;
    g_W16l[(size_t)n*H_ + k] = __float2half_rn((wih0 - __half2float(wh))*2048.0f);

    // LSTM images
    int g = n >> 9, u = n & 511;
    int ct = u >> 2, q = u & 3;
    int n_local = (g < 2) ? (2*q + g) : (2*q + 8 + (g - 2));
    size_t base = (size_t)ct * CTA_IMG_HALVES + (size_t)n_local * WSTRIDE + k;
    __half h0hi = __float2half(whh0);
    __half h0lo = __float2half((whh0 - __half2float(h0hi)) * 2048.0f);
    __half h1hi = __float2half(w1);
    __half h1lo = __float2half((w1 - __half2float(h1hi)) * 2048.0f);
    g_img[base + 0*IMG_HALVES] = h0hi;
    g_img[base + 1*IMG_HALVES] = h0lo;
    g_img[base + 2*IMG_HALVES] = h1hi;
    g_img[base + 3*IMG_HALVES] = h1lo;

    if (k == 0) {
        g_b0[n] = bih0[n] + bhh0[n];
        g_b1[n] = bih1[n] + bhh1[n];
    }
}

// ---------------- build xin ----------------
__global__ void build_xin_kernel(const int* __restrict__ unscaled,
                                 const float* __restrict__ scaled,
                                 const float* __restrict__ emb) {
    int bt = blockIdx.x;
    int i  = threadIdx.x;
    int k  = i / 11;
    int j  = i - k*11;
    float v;
    if (j < 8) {
        int cid = unscaled[(size_t)bt*F_ + 4*k];
        v = emb[(k*CARD_ + cid)*E_ + j];
    } else {
        v = scaled[(size_t)bt*F_ + 4*k + (j - 8) + 1];
    }
    g_xin[(size_t)bt*INPUT_LEN_ + i] = v;
}

// ---------------- gemm1: x = relu(xin@W_in+b), fp32 math, fp16 hi/lo output ----------------
__global__ void __launch_bounds__(256) gemm1_kernel(const float* __restrict__ W_in,
                                                    const float* __restrict__ b_in) {
    __shared__ float AsT[32*132];
    __shared__ float Ws [32*64];
    const int K = INPUT_LEN_, N = H_;
    const int m0 = blockIdx.x * 128;
    const int n0 = blockIdx.y * 64;
    const int tid = threadIdx.x, lane = tid & 31, wid = tid >> 5;
    ull acc[4][4];
    #pragma unroll
    for (int a = 0; a < 4; a++)
        #pragma unroll
        for (int b = 0; b < 4; b++) acc[a][b] = 0ull;

    for (int kb = 0; kb < K; kb += 32) {
        {
            int k = tid & 31, mq = tid >> 5;
            #pragma unroll
            for (int i = 0; i < 16; i++)
                AsT[k*132 + mq + i*8] = g_xin[(size_t)(m0 + mq + i*8)*K + kb + k];
            int n = tid & 63, kq = tid >> 6;
            #pragma unroll
            for (int i = 0; i < 8; i++)
                Ws[(kq*8 + i)*64 + n] = W_in[(size_t)(kb + kq*8 + i)*N + n0 + n];
        }
        __syncthreads();
        #pragma unroll
        for (int kk = 0; kk < 32; kk++) {
            float4 a4 = *(const float4*)(AsT + kk*132 + lane*4);
            const ulonglong2* wp = (const ulonglong2*)(Ws + kk*64 + wid*8);
            ulonglong2 wA = wp[0], wB = wp[1];
            float am[4] = {a4.x, a4.y, a4.z, a4.w};
            #pragma unroll
            for (int mi = 0; mi < 4; mi++) {
                ull ap = pack2(am[mi], am[mi]);
                fma2(acc[mi][0], ap, wA.x);
                fma2(acc[mi][1], ap, wA.y);
                fma2(acc[mi][2], ap, wB.x);
                fma2(acc[mi][3], ap, wB.y);
            }
        }
        __syncthreads();
    }
    const int nb = n0 + wid*8;
    float bv[8];
    #pragma unroll
    for (int j = 0; j < 8; j++) bv[j] = b_in[nb + j];
    #pragma unroll
    for (int mi = 0; mi < 4; mi++) {
        int row = m0 + lane*4 + mi;
        #pragma unroll
        for (int p = 0; p < 4; p++) {
            float2 v = unpack2(acc[mi][p]);
            v.x = fmaxf(v.x + bv[2*p], 0.0f);
            v.y = fmaxf(v.y + bv[2*p+1], 0.0f);
            __half hx = __float2half_rn(v.x), hy = __float2half_rn(v.y);
            __half lx = __float2half_rn((v.x - __half2float(hx))*2048.0f);
            __half ly = __float2half_rn((v.y - __half2float(hy))*2048.0f);
            size_t o = (size_t)row*H_ + nb + 2*p;
            *(__half2*)(g_x16h + o) = __halves2half2(hx, hy);
            *(__half2*)(g_x16l + o) = __halves2half2(lx, ly);
        }
    }
}

// ---------------- gemm2 (HMMA): X0 = x@Wih0^T + b0 ----------------
// CTA tile 128m x 128n, 8 warps (wm = wid&3 m-slice of 32, wn = wid>>2 n-slice of 64),
// warp tile 32m x 64n (mt=2, nt=8). K-step 32, cp.async double buffer.
// X0 = Ah@Wh + (Ah@Wl)/2048; correction accumulated in f16.
#define G2_BUF_B 30720          // 3 tiles * 128*40 halves * 2B
#define G2_A_OFF 0
#define G2_WH_OFF 10240
#define G2_WL_OFF 20480

__device__ __forceinline__ void g2_stage(uint32_t sbase, int buf, int m0, int n0, int kb, int tid) {
    uint32_t b = sbase + buf*G2_BUF_B;
    #pragma unroll
    for (int rep = 0; rep < 2; rep++) {
        int i = rep*256 + tid;
        int row = i >> 2, c = i & 3;
        uint32_t doff = (uint32_t)(row*40 + c*8)*2;
        CP_ASYNC16(b + G2_A_OFF  + doff, g_x16h + (size_t)(m0+row)*H_ + kb + c*8);
        CP_ASYNC16(b + G2_WH_OFF + doff, g_W16h + (size_t)(n0+row)*H_ + kb + c*8);
        CP_ASYNC16(b + G2_WL_OFF + doff, g_W16l + (size_t)(n0+row)*H_ + kb + c*8);
    }
}

__global__ void __launch_bounds__(256) gemm2_kernel() {
    extern __shared__ __half g2s[];
    const int tid = threadIdx.x, lane = tid & 31, wid = tid >> 5;
    const int wm = wid & 3, wn = wid >> 2;
    const int r = lane >> 2, q = lane & 3;
    const int m0 = blockIdx.x * 128;
    const int n0 = blockIdx.y * 128;
    uint32_t sbase = smem_u32(g2s);

    float    accM[2][8][4];
    uint32_t accC[2][8][2];
    #pragma unroll
    for (int mt = 0; mt < 2; mt++)
        #pragma unroll
        for (int nt = 0; nt < 8; nt++) {
            #pragma unroll
            for (int i = 0; i < 4; i++) accM[mt][nt][i] = 0.0f;
            accC[mt][nt][0] = 0u; accC[mt][nt][1] = 0u;
        }

    g2_stage(sbase, 0, m0, n0, 0, tid); CP_COMMIT();

    #pragma unroll 1
    for (int it = 0; it < 16; it++) {
        if (it < 15) { g2_stage(sbase, (it+1)&1, m0, n0, (it+1)*32, tid); CP_COMMIT(); }
        if (it < 15) { CP_WAIT(1); } else { CP_WAIT(0); }
        __syncthreads();
        const __half* sA  = g2s + ((it&1)*G2_BUF_B + G2_A_OFF )/2;
        const __half* sWh = g2s + ((it&1)*G2_BUF_B + G2_WH_OFF)/2;
        const __half* sWl = g2s + ((it&1)*G2_BUF_B + G2_WL_OFF)/2;
        #pragma unroll
        for (int kk = 0; kk < 32; kk += 16) {
            uint32_t a[2][4];
            #pragma unroll
            for (int mt = 0; mt < 2; mt++) {
                const __half* p = sA + (wm*32 + mt*16 + r)*40 + kk + q*2;
                a[mt][0] = *(const uint32_t*)p;
                a[mt][1] = *(const uint32_t*)(p + 8*40);
                a[mt][2] = *(const uint32_t*)(p + 8);
                a[mt][3] = *(const uint32_t*)(p + 8*40 + 8);
            }
            #pragma unroll
            for (int nt = 0; nt < 8; nt++) {
                const __half* ph = sWh + (wn*64 + nt*8 + r)*40 + kk + q*2;
                const __half* pl = sWl + (wn*64 + nt*8 + r)*40 + kk + q*2;
                uint32_t bh[2] = {*(const uint32_t*)ph, *(const uint32_t*)(ph+8)};
                uint32_t bl[2] = {*(const uint32_t*)pl, *(const uint32_t*)(pl+8)};
                #pragma unroll
                for (int mt = 0; mt < 2; mt++) {
                    mma_f32(accM[mt][nt], a[mt], bh);
                    mma_f16acc(accC[mt][nt], a[mt], bl);
                }
            }
        }
        __syncthreads();
    }

    const float s = 1.0f/2048.0f;
    #pragma unroll
    for (int mt = 0; mt < 2; mt++) {
        int gr0 = m0 + wm*32 + mt*16 + r;
        #pragma unroll
        for (int nt = 0; nt < 8; nt++) {
            int col = n0 + wn*64 + nt*8 + q*2;
            float b0a = g_b0[col], b0b = g_b0[col+1];
            __half2 lo01 = *reinterpret_cast<__half2*>(&accC[mt][nt][0]);
            __half2 lo23 = *reinterpret_cast<__half2*>(&accC[mt][nt][1]);
            float2 o0, o1;
            o0.x = accM[mt][nt][0] + __half2float(__low2half(lo01))*s + b0a;
            o0.y = accM[mt][nt][1] + __half2float(__high2half(lo01))*s + b0b;
            o1.x = accM[mt][nt][2] + __half2float(__low2half(lo23))*s + b0a;
            o1.y = accM[mt][nt][3] + __half2float(__high2half(lo23))*s + b0b;
            *(float2*)(g_X0 + (size_t)gr0*G4H_ + col) = o0;
            *(float2*)(g_X0 + (size_t)(gr0+8)*G4H_ + col) = o1;
        }
    }
}

// ---------------- HMMA persistent LSTM (smem-staged A via cp.async + ldmatrix) ----------------
// CTA ct: units [ct*4, ct*4+4), all gates (N=16). Warp w: batches [w*32, w*32+32).
#define SH_OFF CTA_IMG_HALVES          // sH starts after weight images (halves)
#define LSTM_SMEM_B ((CTA_IMG_HALVES + B_*H_)*2)   // 66560 + 131072 = 197632

template<int LAYER>
__device__ __forceinline__ void lstm_phase(int t, int ct, int tid,
                                           const __half* __restrict__ hsrc,
                                           __half* __restrict__ hdst,
                                           const __half* __restrict__ sW,
                                           uint32_t sH_base,
                                           float* __restrict__ creg,
                                           const float* __restrict__ bb) {
    const int w = tid >> 5, lane = tid & 31;
    const int q = lane & 3, r = lane >> 2;
    const int unit = ct*4 + q;

    // prefetch X0 gate biases (layer 0)
    float x0r[2][2][4];
    if (LAYER == 0) {
        #pragma unroll
        for (int mt = 0; mt < 2; mt++)
            #pragma unroll
            for (int hr = 0; hr < 2; hr++) {
                int batch = w*32 + mt*16 + hr*8 + r;
                const float* xb = g_X0 + ((size_t)batch*T_ + t)*G4H_ + unit;
                #pragma unroll
                for (int g = 0; g < 4; g++) x0r[mt][hr][g] = __ldg(xb + g*H_);
            }
    }

    float accH[2][2][4], accL[2][2][4];
    #pragma unroll
    for (int a = 0; a < 2; a++)
        #pragma unroll
        for (int b = 0; b < 2; b++)
            #pragma unroll
            for (int i = 0; i < 4; i++) { accH[a][b][i] = 0.f; accL[a][b][i] = 0.f; }

    // ldmatrix per-lane addressing
    const int arow = w*32 + (lane & 15);
    const uint32_t rowAddr0 = sH_base + arow*1024;
    const uint32_t rowAddr1 = rowAddr0 + 16*1024;
    const int sw = arow & 7;
    const int khalf = lane >> 4;

    const __half* wHi = sW + (LAYER*2 + 0)*IMG_HALVES + r*WSTRIDE + q*2;
    const __half* wLo = wHi + IMG_HALVES;

    // stage chunk j (128 k-cols for all 128 rows, 32KB) via cp.async.cg
    auto stage = [&](int j) {
        #pragma unroll
        for (int it = 0; it < 16; it++) {
            int i = it*128 + tid;
            int row = i >> 4, c = i & 15;
            uint32_t dst = sH_base + row*1024 + (((j*16 + c) ^ (row & 7)) << 4);
            CP_ASYNC16(dst, hsrc + (size_t)row*H_ + (j*16 + c)*8);
        }
    };
    auto mma_chunk = [&](int j) {
        #pragma unroll
        for (int kk = 0; kk < 8; kk++) {
            int k0 = j*128 + kk*16;
            uint32_t coff = (uint32_t)(((j*16 + kk*2 + khalf) ^ sw) << 4);
            uint32_t a0[4], a1[4];
            LDSM_X4(a0[0], a0[1], a0[2], a0[3], rowAddr0 + coff);
            LDSM_X4(a1[0], a1[1], a1[2], a1[3], rowAddr1 + coff);
            #pragma unroll
            for (int nt = 0; nt < 2; nt++) {
                const __half* ph = wHi + nt*8*WSTRIDE + k0;
                const __half* pl = wLo + nt*8*WSTRIDE + k0;
                uint32_t bh[2] = {*(const uint32_t*)ph, *(const uint32_t*)(ph+8)};
                uint32_t bl[2] = {*(const uint32_t*)pl, *(const uint32_t*)(pl+8)};
                mma_f32(accH[0][nt], a0, bh);
                mma_f32(accH[1][nt], a1, bh);
                mma_f32(accL[0][nt], a0, bl);
                mma_f32(accL[1][nt], a1, bl);
            }
        }
    };

    stage(0); CP_COMMIT();
    stage(1); CP_COMMIT();
    stage(2); CP_COMMIT(); CP_WAIT(2); __syncthreads(); mma_chunk(0);
    stage(3); CP_COMMIT(); CP_WAIT(2); __syncthreads(); mma_chunk(1);
    CP_WAIT(1); __syncthreads(); mma_chunk(2);
    CP_WAIT(0); __syncthreads(); mma_chunk(3);

    const float s = 1.0f / 2048.0f;
    #pragma unroll
    for (int mt = 0; mt < 2; mt++) {
        #pragma unroll
        for (int hr = 0; hr < 2; hr++) {
            int batch = w*32 + mt*16 + hr*8 + r;
            float vi = accH[mt][0][hr*2+0] + accL[mt][0][hr*2+0]*s;
            float vf = accH[mt][0][hr*2+1] + accL[mt][0][hr*2+1]*s;
            float vg = accH[mt][1][hr*2+0] + accL[mt][1][hr*2+0]*s;
            float vo = accH[mt][1][hr*2+1] + accL[mt][1][hr*2+1]*s;
            if (LAYER == 0) {
                vi += x0r[mt][hr][0]; vf += x0r[mt][hr][1];
                vg += x0r[mt][hr][2]; vo += x0r[mt][hr][3];
            } else {
                vi += bb[0]; vf += bb[1]; vg += bb[2]; vo += bb[3];
            }
            float c = creg[mt*2 + hr];
            float cn = sigf(vf)*c + sigf(vi)*tanhf(vg);
            creg[mt*2 + hr] = cn;
            float hv = sigf(vo)*tanhf(cn);
            hdst[(size_t)batch*H_ + unit] = __float2half_rn(hv);
            if (LAYER == 1 && t == T_-1) {
                g_h[batch*H_ + unit] = hv;
                g_c[batch*H_ + unit] = cn;
            }
        }
    }
}

__global__ void __launch_bounds__(LSTM_THREADS, 1) lstm_kernel() {
    extern __shared__ __half smemL[];
    __half* sW = smemL;
    uint32_t sH_base = smem_u32(smemL + SH_OFF);
    const int tid = threadIdx.x, lane = tid & 31;
    const int ct = blockIdx.x;

    // copy resident weight images (66560 B)
    {
        const uint4* src = (const uint4*)(g_img + (size_t)ct*CTA_IMG_HALVES);
        uint4* dst = (uint4*)sW;
        #pragma unroll 4
        for (int i = tid; i < CTA_IMG_HALVES/8; i += LSTM_THREADS)
            dst[i] = src[i];
    }
    const int unit = ct*4 + (lane & 3);
    float bb[4];
    #pragma unroll
    for (int g = 0; g < 4; g++) bb[g] = g_b1[g*H_ + unit];

    // zero initial h16 slice (thread = batch, this CTA's 4 units)
    *(uint2*)(g_h16B + (size_t)tid*H_ + ct*4) = make_uint2(0u, 0u);

    __syncthreads();
    float creg[4] = {0.f, 0.f, 0.f, 0.f};
    gsync();   // all h16 slices visible

    for (int t = 0; t < T_; t++) {
        lstm_phase<0>(t, ct, tid, g_h16B, g_h16A, sW, sH_base, creg, bb);
        gsync();
        lstm_phase<1>(t, ct, tid, g_h16A, g_h16B, sW, sH_base, creg, bb);
        gsync();
    }
}

// ---------------- output heads ----------------
__global__ void __launch_bounds__(512) output_kernel(const float* __restrict__ W_out,
                                                     const float* __restrict__ b_out,
                                                     const float* __restrict__ W_cls,
                                                     const float* __restrict__ b_cls,
                                                     float* __restrict__ out) {
    __shared__ float hb[H_];
    int b = blockIdx.x, tid = threadIdx.x;
    hb[tid] = g_h[b*H_ + tid];
    __syncthreads();

    int kk = tid >> 4, cc = tid & 15;
    float acc = 0.0f;
    #pragma unroll 8
    for (int k = 0; k < H_; k++)
        acc = fmaf(hb[k], W_cls[(size_t)kk*H_*CARD_ + k*CARD_ + cc], acc);
    out[12288 + b*512 + tid] = acc + b_cls[tid];

    if (tid < NCONT_) {
        float a2 = 0.0f;
        #pragma unroll 8
        for (int k = 0; k < H_; k++)
            a2 = fmaf(hb[k], W_out[k*NCONT_ + tid], a2);
        out[b*NCONT_ + tid] = a2 + b_out[tid];
    }
    out[77824  + b*512 + tid] = hb[tid];
    out[143360 + b*512 + tid] = g_c[b*H_ + tid];
}

// ---------------- entry ----------------
extern "C" void kernel_launch(void* const* d_in, const int* in_sizes, int n_in,
                              void* d_out, int out_size) {
    (void)in_sizes; (void)n_in; (void)out_size;
    const int*   unscaled = (const int*)  d_in[0];
    const float* scaled   = (const float*)d_in[1];
    const float* emb      = (const float*)d_in[2];
    const float* W_in     = (const float*)d_in[3];
    const float* b_in     = (const float*)d_in[4];
    const float* Wih0     = (const float*)d_in[5];
    const float* Whh0     = (const float*)d_in[6];
    const float* bih0     = (const float*)d_in[7];
    const float* bhh0     = (const float*)d_in[8];
    const float* Wih1     = (const float*)d_in[9];
    const float* Whh1     = (const float*)d_in[10];
    const float* bih1     = (const float*)d_in[11];
    const float* bhh1     = (const float*)d_in[12];
    const float* W_out    = (const float*)d_in[13];
    const float* b_out    = (const float*)d_in[14];
    const float* W_cls    = (const float*)d_in[15];
    const float* b_cls    = (const float*)d_in[16];
    float* out = (float*)d_out;

    cudaFuncSetAttribute(lstm_kernel,  cudaFuncAttributeMaxDynamicSharedMemorySize, LSTM_SMEM_B);
    cudaFuncSetAttribute(gemm2_kernel, cudaFuncAttributeMaxDynamicSharedMemorySize, 2*G2_BUF_B);

    prep_kernel<<<G4H_, H_>>>(Wih0, Whh0, Wih1, Whh1, bih0, bhh0, bih1, bhh1);
    build_xin_kernel<<<BT_, INPUT_LEN_>>>(unscaled, scaled, emb);
    gemm1_kernel<<<dim3(BT_/128, H_/64), 256>>>(W_in, b_in);
    gemm2_kernel<<<dim3(BT_/128, G4H_/128), 256, 2*G2_BUF_B>>>();
    lstm_kernel<<<NBLK_, LSTM_THREADS, LSTM_SMEM_B>>>();
    output_kernel<<<B_, 512>>>(W_out, b_out, W_cls, b_cls, out);
}

// round 7
// speedup vs baseline: 4.6572x; 1.0796x over previous
#include <cuda_runtime.h>
#include <cuda_fp16.h>
#include <cstdint>

#define B_ 128
#define T_ 256
#define F_ 128
#define NCAT_ 32
#define CARD_ 16
#define E_ 8
#define H_ 512
#define INPUT_LEN_ 352
#define NCONT_ 96
#define BT_ (B_*T_)
#define G4H_ 2048
#define NBLK_ 128          // LSTM persistent grid
#define LSTM_THREADS 256
#define WSTRIDE 520        // padded k-stride (halves) for conflict-free weight LDS
#define IMG_HALVES (16*WSTRIDE)
#define CTA_IMG_HALVES (4*IMG_HALVES)

typedef unsigned long long ull;

// ---------------- scratch (device globals) ----------------
__device__ __align__(128) __half g_xin16h[(size_t)BT_*INPUT_LEN_];
__device__ __align__(128) __half g_xin16l[(size_t)BT_*INPUT_LEN_];
__device__ __align__(128) __half g_Win16h[(size_t)H_*INPUT_LEN_];   // W_in^T [n][k] hi
__device__ __align__(128) __half g_Win16l[(size_t)H_*INPUT_LEN_];   // W_in^T residual*2048
__device__ __align__(128) __half g_x16h[(size_t)BT_*H_];
__device__ __align__(128) __half g_x16l[(size_t)BT_*H_];
__device__ __align__(128) float  g_X0 [(size_t)BT_*G4H_];           // x@Wih0^T + bih0 + bhh0
__device__ __align__(128) __half g_W16h[(size_t)G4H_*H_];           // Wih0 fp16 hi, [n][k]
__device__ __align__(128) __half g_W16l[(size_t)G4H_*H_];           // Wih0 residual*2048
__device__ float  g_b0[G4H_];
__device__ float  g_b1[G4H_];
__device__ __align__(128) __half g_img[(size_t)NBLK_*CTA_IMG_HALVES];
__device__ __align__(128) __half g_h16A[B_*H_];   // h0 (layer0 output)
__device__ __align__(128) __half g_h16B[B_*H_];   // h  (layer1 output)
__device__ float  g_h [B_*H_];
__device__ float  g_c [B_*H_];
__device__ unsigned g_bar_count = 0;
__device__ unsigned g_bar_gen   = 0;

// ---------------- helpers ----------------
__device__ __forceinline__ float sigf(float x) { return 1.0f / (1.0f + __expf(-x)); }
__device__ __forceinline__ uint32_t smem_u32(const void* p) {
    uint32_t a;
    asm("{ .reg .u64 t; cvta.to.shared.u64 t, %1; cvt.u32.u64 %0, t; }" : "=r"(a) : "l"(p));
    return a;
}
__device__ __forceinline__ void mma_f32(float* d, const uint32_t* a, const uint32_t* b) {
    asm volatile("mma.sync.aligned.m16n8k16.row.col.f32.f16.f16.f32 "
        "{%0,%1,%2,%3}, {%4,%5,%6,%7}, {%8,%9}, {%0,%1,%2,%3};"
        : "+f"(d[0]), "+f"(d[1]), "+f"(d[2]), "+f"(d[3])
        : "r"(a[0]), "r"(a[1]), "r"(a[2]), "r"(a[3]), "r"(b[0]), "r"(b[1]));
}
__device__ __forceinline__ void mma_f16acc(uint32_t* d, const uint32_t* a, const uint32_t* b) {
    asm volatile("mma.sync.aligned.m16n8k16.row.col.f16.f16.f16.f16 "
        "{%0,%1}, {%2,%3,%4,%5}, {%6,%7}, {%0,%1};"
        : "+r"(d[0]), "+r"(d[1])
        : "r"(a[0]), "r"(a[1]), "r"(a[2]), "r"(a[3]), "r"(b[0]), "r"(b[1]));
}
#define CP_ASYNC16(dst_u32, src_ptr) \
    asm volatile("cp.async.cg.shared.global [%0], [%1], 16;" :: "r"(dst_u32), "l"(src_ptr) : "memory")
#define CP_COMMIT() asm volatile("cp.async.commit_group;" ::: "memory")
#define CP_WAIT(n)  asm volatile("cp.async.wait_group %0;" :: "n"(n) : "memory")
#define LDSM_X4(r0,r1,r2,r3, a) \
    asm volatile("ldmatrix.sync.aligned.m8n8.x4.shared.b16 {%0,%1,%2,%3}, [%4];" \
        : "=r"(r0), "=r"(r1), "=r"(r2), "=r"(r3) : "r"(a))

// grid-wide barrier (NBLK_ CTAs co-resident, 1 CTA/SM)
__device__ __forceinline__ void gsync() {
    __syncthreads();
    if (threadIdx.x == 0) {
        volatile unsigned* genp = &g_bar_gen;
        unsigned gen = *genp;
        __threadfence();
        unsigned t = atomicAdd(&g_bar_count, 1u);
        if (t == (unsigned)NBLK_ - 1u) {
            atomicExch(&g_bar_count, 0u);
            __threadfence();
            atomicAdd(&g_bar_gen, 1u);
        } else {
            while (*genp == gen) { __nanosleep(32); }
        }
        __threadfence();
    }
    __syncthreads();
}

// ---------------- prep ----------------
__global__ void prep_kernel(const float* __restrict__ Wih0, const float* __restrict__ Whh0,
                            const float* __restrict__ Wih1, const float* __restrict__ Whh1,
                            const float* __restrict__ bih0, const float* __restrict__ bhh0,
                            const float* __restrict__ bih1, const float* __restrict__ bhh1) {
    int n = blockIdx.x;      // 0..2047
    int k = threadIdx.x;     // 0..511
    float wih0 = Wih0[n*H_ + k];
    float whh0 = Whh0[n*H_ + k];
    float w1   = Wih1[n*H_ + k] + Whh1[n*H_ + k];

    __half wh = __float2half_rn(wih0);
    g_W16h[(size_t)n*H_ + k] = wh;
    g_W16l[(size_t)n*H_ + k] = __float2half_rn((wih0 - __half2float(wh))*2048.0f);

    int g = n >> 9, u = n & 511;
    int ct = u >> 2, q = u & 3;
    int n_local = (g < 2) ? (2*q + g) : (2*q + 8 + (g - 2));
    size_t base = (size_t)ct * CTA_IMG_HALVES + (size_t)n_local * WSTRIDE + k;
    __half h0hi = __float2half(whh0);
    __half h0lo = __float2half((whh0 - __half2float(h0hi)) * 2048.0f);
    __half h1hi = __float2half(w1);
    __half h1lo = __float2half((w1 - __half2float(h1hi)) * 2048.0f);
    g_img[base + 0*IMG_HALVES] = h0hi;
    g_img[base + 1*IMG_HALVES] = h0lo;
    g_img[base + 2*IMG_HALVES] = h1hi;
    g_img[base + 3*IMG_HALVES] = h1lo;

    if (k == 0) {
        g_b0[n] = bih0[n] + bhh0[n];
        g_b1[n] = bih1[n] + bhh1[n];
    }
}

__global__ void prep_win_kernel(const float* __restrict__ W_in) {
    int k = blockIdx.x;      // 0..351
    int n = threadIdx.x;     // 0..511
    float v = W_in[(size_t)k*H_ + n];
    __half hi = __float2half_rn(v);
    g_Win16h[(size_t)n*INPUT_LEN_ + k] = hi;
    g_Win16l[(size_t)n*INPUT_LEN_ + k] = __float2half_rn((v - __half2float(hi))*2048.0f);
}

// ---------------- build xin (fp16 hi/lo) ----------------
__global__ void build_xin_kernel(const int* __restrict__ unscaled,
                                 const float* __restrict__ scaled,
                                 const float* __restrict__ emb) {
    int bt = blockIdx.x;
    int i  = threadIdx.x;
    int k  = i / 11;
    int j  = i - k*11;
    float v;
    if (j < 8) {
        int cid = unscaled[(size_t)bt*F_ + 4*k];
        v = emb[(k*CARD_ + cid)*E_ + j];
    } else {
        v = scaled[(size_t)bt*F_ + 4*k + (j - 8) + 1];
    }
    __half hi = __float2half_rn(v);
    g_xin16h[(size_t)bt*INPUT_LEN_ + i] = hi;
    g_xin16l[(size_t)bt*INPUT_LEN_ + i] = __float2half_rn((v - __half2float(hi))*2048.0f);
}

// ---------------- HMMA GEMM tiles (shared structure) ----------------
// CTA 128m x 128n, 8 warps (wm=wid&3, wn=wid>>2), warp 32m x 64n, k-step 32, double buffer.
#define GT_BUF_B 30720
#define GT_A_OFF 0
#define GT_WH_OFF 10240
#define GT_WL_OFF 20480

__device__ __forceinline__ void gt_stage(uint32_t sbase, int buf, int m0, int n0, int kb, int tid,
                                         const __half* __restrict__ A, int strideA,
                                         const __half* __restrict__ Wh,
                                         const __half* __restrict__ Wl, int strideW) {
    uint32_t b = sbase + buf*GT_BUF_B;
    #pragma unroll
    for (int rep = 0; rep < 2; rep++) {
        int i = rep*256 + tid;
        int row = i >> 2, c = i & 3;
        uint32_t doff = (uint32_t)(row*40 + c*8)*2;
        CP_ASYNC16(b + GT_A_OFF  + doff, A  + (size_t)(m0+row)*strideA + kb + c*8);
        CP_ASYNC16(b + GT_WH_OFF + doff, Wh + (size_t)(n0+row)*strideW + kb + c*8);
        CP_ASYNC16(b + GT_WL_OFF + doff, Wl + (size_t)(n0+row)*strideW + kb + c*8);
    }
}

template<int KITERS>
__device__ __forceinline__ void gt_mainloop(uint32_t sbase, const __half* g2s,
                                            int m0, int n0, int tid,
                                            const __half* __restrict__ A, int strideA,
                                            const __half* __restrict__ Wh,
                                            const __half* __restrict__ Wl, int strideW,
                                            float accM[2][8][4], uint32_t accC[2][8][2]) {
    const int lane = tid & 31, wid = tid >> 5;
    const int wm = wid & 3, wn = wid >> 2;
    const int r = lane >> 2, q = lane & 3;

    gt_stage(sbase, 0, m0, n0, 0, tid, A, strideA, Wh, Wl, strideW); CP_COMMIT();

    #pragma unroll 1
    for (int it = 0; it < KITERS; it++) {
        if (it < KITERS-1) {
            gt_stage(sbase, (it+1)&1, m0, n0, (it+1)*32, tid, A, strideA, Wh, Wl, strideW);
            CP_COMMIT();
            CP_WAIT(1);
        } else {
            CP_WAIT(0);
        }
        __syncthreads();
        const __half* sA  = g2s + ((it&1)*GT_BUF_B + GT_A_OFF )/2;
        const __half* sWh = g2s + ((it&1)*GT_BUF_B + GT_WH_OFF)/2;
        const __half* sWl = g2s + ((it&1)*GT_BUF_B + GT_WL_OFF)/2;
        #pragma unroll
        for (int kk = 0; kk < 32; kk += 16) {
            uint32_t a[2][4];
            #pragma unroll
            for (int mt = 0; mt < 2; mt++) {
                const __half* p = sA + (wm*32 + mt*16 + r)*40 + kk + q*2;
                a[mt][0] = *(const uint32_t*)p;
                a[mt][1] = *(const uint32_t*)(p + 8*40);
                a[mt][2] = *(const uint32_t*)(p + 8);
                a[mt][3] = *(const uint32_t*)(p + 8*40 + 8);
            }
            #pragma unroll
            for (int nt = 0; nt < 8; nt++) {
                const __half* ph = sWh + (wn*64 + nt*8 + r)*40 + kk + q*2;
                const __half* pl = sWl + (wn*64 + nt*8 + r)*40 + kk + q*2;
                uint32_t bh[2] = {*(const uint32_t*)ph, *(const uint32_t*)(ph+8)};
                uint32_t bl[2] = {*(const uint32_t*)pl, *(const uint32_t*)(pl+8)};
                #pragma unroll
                for (int mt = 0; mt < 2; mt++) {
                    mma_f32(accM[mt][nt], a[mt], bh);
                    mma_f16acc(accC[mt][nt], a[mt], bl);
                }
            }
        }
        __syncthreads();
    }
}

// gemm1: x = relu(xin@W_in + b_in), output fp16 hi/lo
__global__ void __launch_bounds__(256, 2) gemm1_kernel(const float* __restrict__ b_in) {
    extern __shared__ __half g2s[];
    const int tid = threadIdx.x, lane = tid & 31, wid = tid >> 5;
    const int wm = wid & 3, wn = wid >> 2;
    const int r = lane >> 2, q = lane & 3;
    const int m0 = blockIdx.x * 128;
    const int n0 = blockIdx.y * 128;
    uint32_t sbase = smem_u32(g2s);

    float accM[2][8][4]; uint32_t accC[2][8][2];
    #pragma unroll
    for (int mt = 0; mt < 2; mt++)
        #pragma unroll
        for (int nt = 0; nt < 8; nt++) {
            #pragma unroll
            for (int i = 0; i < 4; i++) accM[mt][nt][i] = 0.0f;
            accC[mt][nt][0] = 0u; accC[mt][nt][1] = 0u;
        }

    gt_mainloop<11>(sbase, g2s, m0, n0, tid, g_xin16h, INPUT_LEN_, g_Win16h, g_Win16l, INPUT_LEN_, accM, accC);

    const float s = 1.0f/2048.0f;
    #pragma unroll
    for (int mt = 0; mt < 2; mt++) {
        int gr0 = m0 + wm*32 + mt*16 + r;
        #pragma unroll
        for (int nt = 0; nt < 8; nt++) {
            int col = n0 + wn*64 + nt*8 + q*2;
            float bv0 = b_in[col], bv1 = b_in[col+1];
            __half2 lo01 = *reinterpret_cast<__half2*>(&accC[mt][nt][0]);
            __half2 lo23 = *reinterpret_cast<__half2*>(&accC[mt][nt][1]);
            float v00 = fmaxf(accM[mt][nt][0] + __half2float(__low2half(lo01))*s + bv0, 0.f);
            float v01 = fmaxf(accM[mt][nt][1] + __half2float(__high2half(lo01))*s + bv1, 0.f);
            float v10 = fmaxf(accM[mt][nt][2] + __half2float(__low2half(lo23))*s + bv0, 0.f);
            float v11 = fmaxf(accM[mt][nt][3] + __half2float(__high2half(lo23))*s + bv1, 0.f);
            __half h00 = __float2half_rn(v00), h01 = __float2half_rn(v01);
            __half h10 = __float2half_rn(v10), h11 = __float2half_rn(v11);
            size_t o0 = (size_t)gr0*H_ + col, o1 = (size_t)(gr0+8)*H_ + col;
            *(__half2*)(g_x16h + o0) = __halves2half2(h00, h01);
            *(__half2*)(g_x16l + o0) = __halves2half2(
                __float2half_rn((v00 - __half2float(h00))*2048.f),
                __float2half_rn((v01 - __half2float(h01))*2048.f));
            *(__half2*)(g_x16h + o1) = __halves2half2(h10, h11);
            *(__half2*)(g_x16l + o1) = __halves2half2(
                __float2half_rn((v10 - __half2float(h10))*2048.f),
                __float2half_rn((v11 - __half2float(h11))*2048.f));
        }
    }
}

// gemm2: X0 = x@Wih0^T + b0 (fp32 out)
__global__ void __launch_bounds__(256, 2) gemm2_kernel() {
    extern __shared__ __half g2s[];
    const int tid = threadIdx.x, lane = tid & 31, wid = tid >> 5;
    const int wm = wid & 3, wn = wid >> 2;
    const int r = lane >> 2, q = lane & 3;
    const int m0 = blockIdx.x * 128;
    const int n0 = blockIdx.y * 128;
    uint32_t sbase = smem_u32(g2s);

    float accM[2][8][4]; uint32_t accC[2][8][2];
    #pragma unroll
    for (int mt = 0; mt < 2; mt++)
        #pragma unroll
        for (int nt = 0; nt < 8; nt++) {
            #pragma unroll
            for (int i = 0; i < 4; i++) accM[mt][nt][i] = 0.0f;
            accC[mt][nt][0] = 0u; accC[mt][nt][1] = 0u;
        }

    gt_mainloop<16>(sbase, g2s, m0, n0, tid, g_x16h, H_, g_W16h, g_W16l, H_, accM, accC);

    const float s = 1.0f/2048.0f;
    #pragma unroll
    for (int mt = 0; mt < 2; mt++) {
        int gr0 = m0 + wm*32 + mt*16 + r;
        #pragma unroll
        for (int nt = 0; nt < 8; nt++) {
            int col = n0 + wn*64 + nt*8 + q*2;
            float b0a = g_b0[col], b0b = g_b0[col+1];
            __half2 lo01 = *reinterpret_cast<__half2*>(&accC[mt][nt][0]);
            __half2 lo23 = *reinterpret_cast<__half2*>(&accC[mt][nt][1]);
            float2 o0, o1;
            o0.x = accM[mt][nt][0] + __half2float(__low2half(lo01))*s + b0a;
            o0.y = accM[mt][nt][1] + __half2float(__high2half(lo01))*s + b0b;
            o1.x = accM[mt][nt][2] + __half2float(__low2half(lo23))*s + b0a;
            o1.y = accM[mt][nt][3] + __half2float(__high2half(lo23))*s + b0b;
            *(float2*)(g_X0 + (size_t)gr0*G4H_ + col) = o0;
            *(float2*)(g_X0 + (size_t)(gr0+8)*G4H_ + col) = o1;
        }
    }
}

// ---------------- HMMA persistent LSTM (per-warp private A staging, no intra-phase block sync) ----
// 128 CTAs x 256 threads. CTA ct: units [ct*4, ct*4+4), all gates (N=16). Warp w: batches [w*16, +16).
#define SH_OFF CTA_IMG_HALVES
#define LSTM_SMEM_B ((CTA_IMG_HALVES + B_*H_)*2)   // 66560 + 131072 = 197632

template<int LAYER>
__device__ __forceinline__ void lstm_phase(int t, int ct, int tid,
                                           const __half* __restrict__ hsrc,
                                           __half* __restrict__ hdst,
                                           const __half* __restrict__ sW,
                                           uint32_t sA_base,
                                           float* __restrict__ creg,
                                           const float* __restrict__ bb) {
    const int w = tid >> 5, lane = tid & 31;
    const int q = lane & 3, r = lane >> 2;
    const int unit = ct*4 + q;
    const uint32_t wbase = sA_base + (uint32_t)w*16384;

    // stage this warp's 16 h-rows (4 chunks of 128 k-cols), private buffer
    #pragma unroll
    for (int j = 0; j < 4; j++) {
        #pragma unroll
        for (int seg = 0; seg < 8; seg++) {
            int i = seg*32 + lane;
            int rl = i >> 4, c = i & 15;
            uint32_t dst = wbase + rl*1024 + ((uint32_t)((j*16 + c) ^ (rl & 7)) << 4);
            CP_ASYNC16(dst, hsrc + (size_t)(w*16 + rl)*H_ + (j*16 + c)*8);
        }
        CP_COMMIT();
    }

    // X0 / bias prefetch (overlaps with staging)
    float x0r[2][4];
    if (LAYER == 0) {
        #pragma unroll
        for (int hr = 0; hr < 2; hr++) {
            int batch = w*16 + hr*8 + r;
            const float* xb = g_X0 + ((size_t)batch*T_ + t)*G4H_ + unit;
            #pragma unroll
            for (int g = 0; g < 4; g++) x0r[hr][g] = __ldg(xb + g*H_);
        }
    }

    float accH[2][4], accL[2][4];
    #pragma unroll
    for (int nt = 0; nt < 2; nt++)
        #pragma unroll
        for (int i = 0; i < 4; i++) { accH[nt][i] = 0.f; accL[nt][i] = 0.f; }

    const uint32_t rowAddr = wbase + (uint32_t)(lane & 15)*1024;
    const int sw = lane & 7;
    const int khalf = lane >> 4;
    const __half* wHi = sW + (LAYER*2 + 0)*IMG_HALVES + r*WSTRIDE + q*2;
    const __half* wLo = wHi + IMG_HALVES;

    auto mma_chunk = [&](int j) {
        #pragma unroll
        for (int kk = 0; kk < 8; kk++) {
            int k0 = j*128 + kk*16;
            uint32_t coff = ((uint32_t)((j*16 + kk*2 + khalf) ^ sw)) << 4;
            uint32_t a[4];
            LDSM_X4(a[0], a[1], a[2], a[3], rowAddr + coff);
            #pragma unroll
            for (int nt = 0; nt < 2; nt++) {
                const __half* ph = wHi + nt*8*WSTRIDE + k0;
                const __half* pl = wLo + nt*8*WSTRIDE + k0;
                uint32_t bh[2] = {*(const uint32_t*)ph, *(const uint32_t*)(ph+8)};
                uint32_t bl[2] = {*(const uint32_t*)pl, *(const uint32_t*)(pl+8)};
                mma_f32(accH[nt], a, bh);
                mma_f32(accL[nt], a, bl);
            }
        }
    };

    CP_WAIT(3); __syncwarp(); mma_chunk(0);
    CP_WAIT(2); __syncwarp(); mma_chunk(1);
    CP_WAIT(1); __syncwarp(); mma_chunk(2);
    CP_WAIT(0); __syncwarp(); mma_chunk(3);

    const float s = 1.0f / 2048.0f;
    #pragma unroll
    for (int hr = 0; hr < 2; hr++) {
        int batch = w*16 + hr*8 + r;
        float vi = accH[0][hr*2+0] + accL[0][hr*2+0]*s;
        float vf = accH[0][hr*2+1] + accL[0][hr*2+1]*s;
        float vg = accH[1][hr*2+0] + accL[1][hr*2+0]*s;
        float vo = accH[1][hr*2+1] + accL[1][hr*2+1]*s;
        if (LAYER == 0) {
            vi += x0r[hr][0]; vf += x0r[hr][1]; vg += x0r[hr][2]; vo += x0r[hr][3];
        } else {
            vi += bb[0]; vf += bb[1]; vg += bb[2]; vo += bb[3];
        }
        float c = creg[hr];
        float cn = sigf(vf)*c + sigf(vi)*tanhf(vg);
        creg[hr] = cn;
        float hv = sigf(vo)*tanhf(cn);
        hdst[(size_t)batch*H_ + unit] = __float2half_rn(hv);
        if (LAYER == 1 && t == T_-1) {
            g_h[batch*H_ + unit] = hv;
            g_c[batch*H_ + unit] = cn;
        }
    }
}

__global__ void __launch_bounds__(LSTM_THREADS, 1) lstm_kernel() {
    extern __shared__ __half smemL[];
    __half* sW = smemL;
    uint32_t sA_base = smem_u32(smemL + SH_OFF);
    const int tid = threadIdx.x, lane = tid & 31;
    const int ct = blockIdx.x;

    // copy resident weight images (66560 B)
    {
        const uint4* src = (const uint4*)(g_img + (size_t)ct*CTA_IMG_HALVES);
        uint4* dst = (uint4*)sW;
        #pragma unroll 4
        for (int i = tid; i < CTA_IMG_HALVES/8; i += LSTM_THREADS)
            dst[i] = src[i];
    }
    const int unit = ct*4 + (lane & 3);
    float bb[4];
    #pragma unroll
    for (int g = 0; g < 4; g++) bb[g] = g_b1[g*H_ + unit];

    // zero initial h16 slice (threads 0..127 = batches)
    if (tid < B_)
        *(uint2*)(g_h16B + (size_t)tid*H_ + ct*4) = make_uint2(0u, 0u);

    __syncthreads();
    float creg[2] = {0.f, 0.f};
    gsync();   // all h16 slices visible

    for (int t = 0; t < T_; t++) {
        lstm_phase<0>(t, ct, tid, g_h16B, g_h16A, sW, sA_base, creg, bb);
        gsync();
        lstm_phase<1>(t, ct, tid, g_h16A, g_h16B, sW, sA_base, creg, bb);
        gsync();
    }
}

// ---------------- output heads ----------------
__global__ void __launch_bounds__(512) output_kernel(const float* __restrict__ W_out,
                                                     const float* __restrict__ b_out,
                                                     const float* __restrict__ W_cls,
                                                     const float* __restrict__ b_cls,
                                                     float* __restrict__ out) {
    __shared__ float hb[H_];
    int b = blockIdx.x, tid = threadIdx.x;
    hb[tid] = g_h[b*H_ + tid];
    __syncthreads();

    int kk = tid >> 4, cc = tid & 15;
    float acc = 0.0f;
    #pragma unroll 8
    for (int k = 0; k < H_; k++)
        acc = fmaf(hb[k], W_cls[(size_t)kk*H_*CARD_ + k*CARD_ + cc], acc);
    out[12288 + b*512 + tid] = acc + b_cls[tid];

    if (tid < NCONT_) {
        float a2 = 0.0f;
        #pragma unroll 8
        for (int k = 0; k < H_; k++)
            a2 = fmaf(hb[k], W_out[k*NCONT_ + tid], a2);
        out[b*NCONT_ + tid] = a2 + b_out[tid];
    }
    out[77824  + b*512 + tid] = hb[tid];
    out[143360 + b*512 + tid] = g_c[b*H_ + tid];
}

// ---------------- entry ----------------
extern "C" void kernel_launch(void* const* d_in, const int* in_sizes, int n_in,
                              void* d_out, int out_size) {
    (void)in_sizes; (void)n_in; (void)out_size;
    const int*   unscaled = (const int*)  d_in[0];
    const float* scaled   = (const float*)d_in[1];
    const float* emb      = (const float*)d_in[2];
    const float* W_in     = (const float*)d_in[3];
    const float* b_in     = (const float*)d_in[4];
    const float* Wih0     = (const float*)d_in[5];
    const float* Whh0     = (const float*)d_in[6];
    const float* bih0     = (const float*)d_in[7];
    const float* bhh0     = (const float*)d_in[8];
    const float* Wih1     = (const float*)d_in[9];
    const float* Whh1     = (const float*)d_in[10];
    const float* bih1     = (const float*)d_in[11];
    const float* bhh1     = (const float*)d_in[12];
    const float* W_out    = (const float*)d_in[13];
    const float* b_out    = (const float*)d_in[14];
    const float* W_cls    = (const float*)d_in[15];
    const float* b_cls    = (const float*)d_in[16];
    float* out = (float*)d_out;

    cudaFuncSetAttribute(lstm_kernel,  cudaFuncAttributeMaxDynamicSharedMemorySize, LSTM_SMEM_B);
    cudaFuncSetAttribute(gemm1_kernel, cudaFuncAttributeMaxDynamicSharedMemorySize, 2*GT_BUF_B);
    cudaFuncSetAttribute(gemm2_kernel, cudaFuncAttributeMaxDynamicSharedMemorySize, 2*GT_BUF_B);

    prep_kernel<<<G4H_, H_>>>(Wih0, Whh0, Wih1, Whh1, bih0, bhh0, bih1, bhh1);
    prep_win_kernel<<<INPUT_LEN_, H_>>>(W_in);
    build_xin_kernel<<<BT_, INPUT_LEN_>>>(unscaled, scaled, emb);
    gemm1_kernel<<<dim3(BT_/128, H_/128), 256, 2*GT_BUF_B>>>(b_in);
    gemm2_kernel<<<dim3(BT_/128, G4H_/128), 256, 2*GT_BUF_B>>>();
    lstm_kernel<<<NBLK_, LSTM_THREADS, LSTM_SMEM_B>>>();
    output_kernel<<<B_, 512>>>(W_out, b_out, W_cls, b_cls, out);
}